// round 14
// baseline (speedup 1.0000x reference)
#include <cuda_runtime.h>
#include <cuda_bf16.h>
#include <math.h>
#include <stdint.h>

// Problem constants
#define TT 512
#define BB 256
#define IN_DIM 256
#define H1 512
#define HH 256
#define OUT_DIM 18
#define MTOT (TT*BB)   // 131072
#define NCTA_GRU 64
#define NCTA_ALL 148
#define NWORK (NCTA_ALL - NCTA_GRU)   // 84
#define GRP 8          // CTAs per sync group

// -------------------- scratch (static device globals; no allocs) -----------
__device__ float d_buf1[(size_t)MTOT * 512];     // fc2a out (fp32, for head)
__device__ float d_GI  [(size_t)MTOT * 768];     // gi fp32

__device__ __nv_bfloat16 d_XHI[(size_t)MTOT * 256], d_XLO[(size_t)MTOT * 256];
__device__ __nv_bfloat16 d_A1HI[(size_t)MTOT * 512], d_A1LO[(size_t)MTOT * 512];
__device__ __nv_bfloat16 d_A2HI[(size_t)MTOT * 256], d_A2LO[(size_t)MTOT * 256];
__device__ __nv_bfloat16 d_HHI[(size_t)MTOT * 256], d_HLO[(size_t)MTOT * 256];

__device__ __nv_bfloat16 d_W1AHI[512*256], d_W1ALO[512*256];
__device__ __nv_bfloat16 d_W1BHI[256*512], d_W1BLO[256*512];
__device__ __nv_bfloat16 d_WIHHI[768*256], d_WIHLO[768*256];
__device__ __nv_bfloat16 d_W2AHI[512*256], d_W2ALO[512*256];
__device__ __nv_bfloat16 d_WHHHI[768*256], d_WHHLO[768*256];

// padded sync state: one 128B line per slot
__device__ unsigned int d_flags[NCTA_GRU * 2 * 32];
__device__ unsigned int d_gicnt[TT * 32];
__device__ unsigned int d_facnt[TT * 32];
__device__ unsigned int d_fbcnt[TT * 32];

// ==================== helpers ==============================================
__device__ __forceinline__ uint32_t smem_u32(const void* p) {
    uint32_t a;
    asm("{ .reg .u64 t; cvta.to.shared.u64 t, %1; cvt.u32.u64 %0, t; }"
        : "=r"(a) : "l"(p));
    return a;
}

__device__ __forceinline__ void ldsm4(uint32_t* r, uint32_t addr) {
    asm volatile("ldmatrix.sync.aligned.m8n8.x4.shared.b16 {%0,%1,%2,%3}, [%4];"
        : "=r"(r[0]), "=r"(r[1]), "=r"(r[2]), "=r"(r[3]) : "r"(addr));
}
__device__ __forceinline__ void ldsm2(uint32_t* r, uint32_t addr) {
    asm volatile("ldmatrix.sync.aligned.m8n8.x2.shared.b16 {%0,%1}, [%2];"
        : "=r"(r[0]), "=r"(r[1]) : "r"(addr));
}

__device__ __forceinline__ void mma16816(float* c, const uint32_t* a, const uint32_t* b) {
    asm volatile(
        "mma.sync.aligned.m16n8k16.row.col.f32.bf16.bf16.f32 "
        "{%0,%1,%2,%3}, {%4,%5,%6,%7}, {%8,%9}, {%0,%1,%2,%3};"
        : "+f"(c[0]), "+f"(c[1]), "+f"(c[2]), "+f"(c[3])
        : "r"(a[0]), "r"(a[1]), "r"(a[2]), "r"(a[3]), "r"(b[0]), "r"(b[1]));
}

__device__ __forceinline__ void cp16(uint32_t dst, const void* src) {
    asm volatile("cp.async.cg.shared.global [%0], [%1], 16;"
        :: "r"(dst), "l"(src) : "memory");
}
#define CP_COMMIT() asm volatile("cp.async.commit_group;" ::: "memory")
#define CP_WAIT0()  asm volatile("cp.async.wait_group 0;" ::: "memory")
#define CP_WAIT1()  asm volatile("cp.async.wait_group 1;" ::: "memory")
#define BARX(id)    asm volatile("bar.sync %0, 128;" :: "r"(id) : "memory")

__device__ __forceinline__ void split_bf16x4(float4 v, uint2& hv, uint2& lv) {
    __nv_bfloat16 h0 = __float2bfloat16(v.x);
    __nv_bfloat16 h1 = __float2bfloat16(v.y);
    __nv_bfloat16 h2 = __float2bfloat16(v.z);
    __nv_bfloat16 h3 = __float2bfloat16(v.w);
    __nv_bfloat16 l0 = __float2bfloat16(v.x - __bfloat162float(h0));
    __nv_bfloat16 l1 = __float2bfloat16(v.y - __bfloat162float(h1));
    __nv_bfloat16 l2 = __float2bfloat16(v.z - __bfloat162float(h2));
    __nv_bfloat16 l3 = __float2bfloat16(v.w - __bfloat162float(h3));
    hv.x = (uint32_t)__bfloat16_as_ushort(h0) | ((uint32_t)__bfloat16_as_ushort(h1) << 16);
    hv.y = (uint32_t)__bfloat16_as_ushort(h2) | ((uint32_t)__bfloat16_as_ushort(h3) << 16);
    lv.x = (uint32_t)__bfloat16_as_ushort(l0) | ((uint32_t)__bfloat16_as_ushort(l1) << 16);
    lv.y = (uint32_t)__bfloat16_as_ushort(l2) | ((uint32_t)__bfloat16_as_ushort(l3) << 16);
}

__device__ __forceinline__ uint32_t pack_hi2(float a, float b, uint32_t& lo) {
    __nv_bfloat16 ha = __float2bfloat16(a);
    __nv_bfloat16 hb = __float2bfloat16(b);
    __nv_bfloat16 la = __float2bfloat16(a - __bfloat162float(ha));
    __nv_bfloat16 lb = __float2bfloat16(b - __bfloat162float(hb));
    lo = (uint32_t)__bfloat16_as_ushort(la) | ((uint32_t)__bfloat16_as_ushort(lb) << 16);
    return (uint32_t)__bfloat16_as_ushort(ha) | ((uint32_t)__bfloat16_as_ushort(hb) << 16);
}

// -------------------- split / zero kernels ---------------------------------
__global__ void split_f32(const float4* __restrict__ in,
                          uint2* __restrict__ hi, uint2* __restrict__ lo, int n4) {
    int i = blockIdx.x * blockDim.x + threadIdx.x;
    if (i < n4) {
        uint2 h, l;
        split_bf16x4(in[i], h, l);
        hi[i] = h; lo[i] = l;
    }
}
__global__ void zero_u32(uint32_t* p, int n) {
    int i = blockIdx.x * blockDim.x + threadIdx.x;
    if (i < n) p[i] = 0u;
}

// ==================== persistent everything kernel ==========================
// 148 CTAs: 0-63 GRU producers (R12 code); 64-147 workers running a t-major
// producer stream (fc1a -> fc1b -> gi, counter-gated) then the fc2a phase.
#define GROW 144
#define G_AHI 0
#define G_ALO 18432
#define G_BHI 36864
#define G_BLO 55296
#define G_STAGE 73728
#define G_SM_TOTAL (2*G_STAGE)

#define U_WHI 0
#define U_WLO 50688            // 96*528
#define U_HA_HI 101376         // 16*528 = 8448 each
#define U_HA_LO 109824
#define U_HB_HI 118272
#define U_HB_LO 126720
#define U_GHA 135168           // 16*97*4 = 6208
#define U_GHB 141376
#define U_SM_TOTAL 147584      // >= G_SM_TOTAL for worker path
#define USTRIDE 528

__global__ void __launch_bounds__(256, 1) gru_persist(
    float* __restrict__ GI_,
    const __nv_bfloat16* __restrict__ whh_hi,
    const __nv_bfloat16* __restrict__ whh_lo,
    const float* __restrict__ bhh,
    __nv_bfloat16* __restrict__ HHI_,
    __nv_bfloat16* __restrict__ HLO_,
    unsigned int* __restrict__ flags,
    const __nv_bfloat16* __restrict__ w2a_hi,
    const __nv_bfloat16* __restrict__ w2a_lo,
    const float* __restrict__ b2a,
    float* __restrict__ buf1,
    __nv_bfloat16* __restrict__ a2_hi,
    __nv_bfloat16* __restrict__ a2_lo,
    const __nv_bfloat16* __restrict__ wih_hi,
    const __nv_bfloat16* __restrict__ wih_lo,
    const float* __restrict__ bih,
    unsigned int* __restrict__ gicnt,
    const __nv_bfloat16* __restrict__ xhi,
    const __nv_bfloat16* __restrict__ xlo,
    const __nv_bfloat16* __restrict__ w1a_hi,
    const __nv_bfloat16* __restrict__ w1a_lo,
    const float* __restrict__ b1a,
    __nv_bfloat16* __restrict__ a1_hi,
    __nv_bfloat16* __restrict__ a1_lo,
    const __nv_bfloat16* __restrict__ w1b_hi,
    const __nv_bfloat16* __restrict__ w1b_lo,
    const float* __restrict__ b1b,
    unsigned int* __restrict__ facnt,
    unsigned int* __restrict__ fbcnt)
{
    extern __shared__ char sm[];
    const uint32_t smb = smem_u32(sm);
    const int tid = threadIdx.x;
    const int lane = tid & 31;
    const int wid = tid >> 5;
    const int cta = blockIdx.x;

    if (cta < NCTA_GRU) {
        // ==================== GRU producer path (R12, proven) ===============
        const int grpB = wid >> 2;
        const int gtid = tid & 127;
        const int wn = wid & 3;
        const int grp = cta >> 3;
        const int kq  = cta & 7;
        const int b0 = grp * 32;
        const int k0 = kq * 32;
        const int barid = 1 + grpB;

        float* GHg = (float*)(sm + (grpB ? U_GHB : U_GHA));
        const uint32_t hHiBuf = smb + (grpB ? U_HB_HI : U_HA_HI);
        const uint32_t hLoBuf = smb + (grpB ? U_HB_LO : U_HA_LO);
        const int bOff = grpB ? 16 : 0;

        for (int i = tid; i < 3072; i += 256) {
            int j = i >> 5;
            int c = i & 31;
            int gate = j >> 5, jr = j & 31;
            size_t soff = (size_t)(gate * 256 + k0 + jr) * 256 + c * 8;
            uint32_t d = (uint32_t)(j * USTRIDE + c * 16);
            cp16(smb + U_WHI + d, whh_hi + soff);
            cp16(smb + U_WLO + d, whh_lo + soff);
        }
        CP_COMMIT();

        {
            float* GA = (float*)(sm + U_GHA);
            float* GB = (float*)(sm + U_GHB);
            for (int i = tid; i < 16 * 97; i += 256) { GA[i] = 0.f; GB[i] = 0.f; }
        }

        int bloc[4], kloc[4];
        size_t off_o[4], gio[4];
        float brr[4], brz[4], brn[4], hp[4];
        #pragma unroll
        for (int i = 0; i < 4; i++) {
            int idx = gtid + 128 * i;
            int b = idx >> 5, ko = idx & 31;
            bloc[i] = b; kloc[i] = ko;
            int kg = k0 + ko;
            off_o[i] = (size_t)(b0 + bOff + b) * 256 + kg;
            gio[i] = (size_t)(b0 + bOff + b) * 768 + kg;
            brr[i] = bhh[kg];
            brz[i] = bhh[256 + kg];
            brn[i] = bhh[512 + kg];
            hp[i] = 0.f;
        }

        const uint32_t a_row = (uint32_t)(lane & 15);
        const uint32_t a_kb  = (uint32_t)((lane >> 4) * 16);
        const uint32_t b_row = (uint32_t)(((lane >> 4) & 1) * 8 + (lane & 7));
        const uint32_t b_kb  = (uint32_t)(((lane >> 3) & 1) * 16);
        const uint32_t b2_row = (uint32_t)(lane & 7);
        const uint32_t b2_kb  = (uint32_t)(((lane >> 3) & 1) * 16);

        const uint32_t aHi = hHiBuf + a_row * USTRIDE + a_kb;
        const uint32_t aLo = hLoBuf + a_row * USTRIDE + a_kb;
        const uint32_t bBaseHi4 = smb + U_WHI + (uint32_t)(wn * 24 + b_row) * USTRIDE + b_kb;
        const uint32_t bBaseLo4 = smb + U_WLO + (uint32_t)(wn * 24 + b_row) * USTRIDE + b_kb;
        const uint32_t bBaseHi2 = smb + U_WHI + (uint32_t)(wn * 24 + 16 + b2_row) * USTRIDE + b2_kb;
        const uint32_t bBaseLo2 = smb + U_WLO + (uint32_t)(wn * 24 + 16 + b2_row) * USTRIDE + b2_kb;

        unsigned int* myflag = flags + (cta * 2 + grpB) * 32;
        unsigned int* poll   = flags + (((grp * GRP) + (gtid & 7)) * 2 + grpB) * 32;

        auto do_mma = [&]() {
            float acc[3][4];
            #pragma unroll
            for (int i = 0; i < 3; i++)
                #pragma unroll
                for (int e = 0; e < 4; e++) acc[i][e] = 0.f;

            #pragma unroll 4
            for (int ks = 0; ks < 16; ks++) {
                const uint32_t koff = (uint32_t)(ks * 32);
                uint32_t a[4], bh[3][2], bl[3][2], r4[4];

                ldsm4(a, aHi + koff);
                ldsm4(r4, bBaseHi4 + koff);
                bh[0][0] = r4[0]; bh[0][1] = r4[1]; bh[1][0] = r4[2]; bh[1][1] = r4[3];
                ldsm2(bh[2], bBaseHi2 + koff);
                #pragma unroll
                for (int nt = 0; nt < 3; nt++) mma16816(acc[nt], a, bh[nt]);

                ldsm4(r4, bBaseLo4 + koff);
                bl[0][0] = r4[0]; bl[0][1] = r4[1]; bl[1][0] = r4[2]; bl[1][1] = r4[3];
                ldsm2(bl[2], bBaseLo2 + koff);
                #pragma unroll
                for (int nt = 0; nt < 3; nt++) mma16816(acc[nt], a, bl[nt]);

                ldsm4(a, aLo + koff);
                #pragma unroll
                for (int nt = 0; nt < 3; nt++) mma16816(acc[nt], a, bh[nt]);
            }
            const int r0 = lane >> 2;
            const int cc = (lane & 3) * 2;
            #pragma unroll
            for (int nt = 0; nt < 3; nt++) {
                int col = wn * 24 + nt * 8 + cc;
                GHg[r0 * 97 + col]           = acc[nt][0];
                GHg[r0 * 97 + col + 1]       = acc[nt][1];
                GHg[(r0 + 8) * 97 + col]     = acc[nt][2];
                GHg[(r0 + 8) * 97 + col + 1] = acc[nt][3];
            }
        };

        float ir[4], iz[4], in_[4];
        auto wait_gi = [&](int t) {
            const unsigned int* c = gicnt + t * 32;
            unsigned int v;
            do {
                asm volatile("ld.acquire.gpu.u32 %0, [%1];"
                    : "=r"(v) : "l"(c) : "memory");
            } while (v < 12u);
        };
        auto prefetch_gi = [&](int t) {
            const float* gin = GI_ + (size_t)t * (BB * 768);
            #pragma unroll
            for (int i = 0; i < 4; i++) {
                ir[i]  = __ldg(gin + gio[i]);
                iz[i]  = __ldg(gin + gio[i] + 256);
                in_[i] = __ldg(gin + gio[i] + 512);
            }
        };

        auto do_gates = [&](int t) {
            __nv_bfloat16* hoh = HHI_ + (size_t)t * (BB * HH);
            __nv_bfloat16* hol = HLO_ + (size_t)t * (BB * HH);
            #pragma unroll
            for (int i = 0; i < 4; i++) {
                int b = bloc[i], ko = kloc[i];
                float hr = GHg[b * 97 + ko]      + brr[i];
                float hz = GHg[b * 97 + 32 + ko] + brz[i];
                float hn = GHg[b * 97 + 64 + ko] + brn[i];

                float r = 1.f / (1.f + __expf(-(ir[i] + hr)));
                float z = 1.f / (1.f + __expf(-(iz[i] + hz)));
                float n = tanhf(in_[i] + r * hn);
                float hnew = (1.f - z) * n + z * hp[i];
                hp[i] = hnew;

                __nv_bfloat16 hh = __float2bfloat16(hnew);
                hoh[off_o[i]] = hh;
                hol[off_o[i]] = __float2bfloat16(hnew - __bfloat162float(hh));
            }
        };

        auto load_h = [&](int t) {
            const __nv_bfloat16* hph = HHI_ + (size_t)t * (BB * HH);
            const __nv_bfloat16* hpl = HLO_ + (size_t)t * (BB * HH);
            #pragma unroll
            for (int i = 0; i < 4; i++) {
                int idx = gtid + 128 * i;
                int r = idx >> 5;
                int c = idx & 31;
                size_t soff = (size_t)(b0 + bOff + r) * 256 + c * 8;
                uint32_t d = (uint32_t)(r * USTRIDE + c * 16);
                cp16(hHiBuf + d, hph + soff);
                cp16(hLoBuf + d, hpl + soff);
            }
            CP_COMMIT();
        };

        auto signal_spin = [&](unsigned int target) {
            BARX(barid);
            if (gtid == 0) {
                asm volatile("st.release.gpu.u32 [%0], %1;"
                    :: "l"(myflag), "r"(target) : "memory");
            }
            if (gtid < GRP) {
                unsigned int v;
                do {
                    asm volatile("ld.acquire.gpu.u32 %0, [%1];"
                        : "=r"(v) : "l"(poll) : "memory");
                } while (v < target);
            }
            BARX(barid);
        };

        CP_WAIT0();
        __syncthreads();

        wait_gi(0);
        prefetch_gi(0);
        do_gates(0);
        wait_gi(1);
        prefetch_gi(1);
        signal_spin(1u);
        load_h(0);

        for (int t = 1; t < TT; t++) {
            CP_WAIT0();
            BARX(barid);
            do_mma();
            BARX(barid);
            do_gates(t);
            if (t + 1 < TT) {
                wait_gi(t + 1);
                prefetch_gi(t + 1);
                signal_spin((unsigned int)(t + 1));
                load_h(t);
            }
        }
        BARX(barid);
        if (gtid == 0) {
            asm volatile("st.release.gpu.u32 [%0], %1;"
                :: "l"(myflag), "r"((unsigned int)TT) : "memory");
        }
    } else {
        // ==================== worker path ===================================
        const int wrk = cta - NCTA_GRU;
        const int wm = wid & 1;
        const int wn = wid >> 1;
        const uint32_t a_row = (uint32_t)(lane & 15);
        const uint32_t a_kb  = (uint32_t)((lane >> 4) * 16);
        const uint32_t b_row = (uint32_t)(((lane >> 4) & 1) * 8 + (lane & 7));
        const uint32_t b_kb  = (uint32_t)(((lane >> 3) & 1) * 16);
        const int r_in = lane >> 2;
        const int c_in = (lane & 3) * 2;

        auto spin_cnt = [&](unsigned int* c, unsigned int tgt) {
            if (tid == 0) {
                unsigned int v;
                do {
                    asm volatile("ld.acquire.gpu.u32 %0, [%1];"
                        : "=r"(v) : "l"(c) : "memory");
                } while (v < tgt);
            }
            __syncthreads();
        };
        auto bump_cnt = [&](unsigned int* c) {
            __threadfence();
            __syncthreads();
            if (tid == 0)
                asm volatile("red.release.gpu.global.add.u32 [%0], %1;"
                    :: "l"(c), "r"(1u) : "memory");
        };

        // generic 128x128xK bf16-split tile
        auto do_tile = [&](const __nv_bfloat16* Ahi_, const __nv_bfloat16* Alo_,
                           size_t m0, int Ks, int nch,
                           const __nv_bfloat16* Bhi_, const __nv_bfloat16* Blo_,
                           int n0, const float* bias_,
                           float* outF, __nv_bfloat16* outHi, __nv_bfloat16* outLo,
                           int outN, bool relu) {
            float acc[4][4][4];
            #pragma unroll
            for (int i = 0; i < 4; i++)
                #pragma unroll
                for (int j = 0; j < 4; j++)
                    #pragma unroll
                    for (int e = 0; e < 4; e++) acc[i][j][e] = 0.f;

            auto load_chunk = [&](int kc, int st) {
                const int kb = kc << 6;
                const uint32_t base = smb + (uint32_t)st * G_STAGE;
                #pragma unroll
                for (int j = 0; j < 4; j++) {
                    int idx = tid + 256 * j;
                    int r = idx >> 3;
                    int c = idx & 7;
                    size_t aoff = (m0 + r) * (size_t)Ks + kb + c * 8;
                    size_t boff = (size_t)(n0 + r) * Ks + kb + c * 8;
                    uint32_t d = (uint32_t)(r * GROW + c * 16);
                    cp16(base + G_AHI + d, Ahi_ + aoff);
                    cp16(base + G_ALO + d, Alo_ + aoff);
                    cp16(base + G_BHI + d, Bhi_ + boff);
                    cp16(base + G_BLO + d, Blo_ + boff);
                }
                CP_COMMIT();
            };

            load_chunk(0, 0);
            for (int kc = 0; kc < nch; kc++) {
                const int st = kc & 1;
                if (kc + 1 < nch) { load_chunk(kc + 1, st ^ 1); CP_WAIT1(); }
                else              { CP_WAIT0(); }
                __syncthreads();

                const uint32_t base = smb + (uint32_t)st * G_STAGE;
                #pragma unroll
                for (int ks = 0; ks < 4; ks++) {
                    const uint32_t koff = (uint32_t)(ks * 32);
                    uint32_t afr[4][4], bhi2[4][2], blo2[4][2];

                    #pragma unroll
                    for (int mt = 0; mt < 4; mt++)
                        ldsm4(afr[mt], base + G_AHI + (uint32_t)(wm*64 + mt*16 + a_row)*GROW + koff + a_kb);
                    #pragma unroll
                    for (int g = 0; g < 2; g++) {
                        uint32_t r4[4];
                        ldsm4(r4, base + G_BHI + (uint32_t)(wn*32 + g*16 + b_row)*GROW + koff + b_kb);
                        bhi2[g*2  ][0] = r4[0]; bhi2[g*2  ][1] = r4[1];
                        bhi2[g*2+1][0] = r4[2]; bhi2[g*2+1][1] = r4[3];
                    }
                    #pragma unroll
                    for (int mt = 0; mt < 4; mt++)
                        #pragma unroll
                        for (int nt = 0; nt < 4; nt++)
                            mma16816(acc[mt][nt], afr[mt], bhi2[nt]);

                    #pragma unroll
                    for (int g = 0; g < 2; g++) {
                        uint32_t r4[4];
                        ldsm4(r4, base + G_BLO + (uint32_t)(wn*32 + g*16 + b_row)*GROW + koff + b_kb);
                        blo2[g*2  ][0] = r4[0]; blo2[g*2  ][1] = r4[1];
                        blo2[g*2+1][0] = r4[2]; blo2[g*2+1][1] = r4[3];
                    }
                    #pragma unroll
                    for (int mt = 0; mt < 4; mt++)
                        #pragma unroll
                        for (int nt = 0; nt < 4; nt++)
                            mma16816(acc[mt][nt], afr[mt], blo2[nt]);

                    #pragma unroll
                    for (int mt = 0; mt < 4; mt++)
                        ldsm4(afr[mt], base + G_ALO + (uint32_t)(wm*64 + mt*16 + a_row)*GROW + koff + a_kb);
                    #pragma unroll
                    for (int mt = 0; mt < 4; mt++)
                        #pragma unroll
                        for (int nt = 0; nt < 4; nt++)
                            mma16816(acc[mt][nt], afr[mt], bhi2[nt]);
                }
                __syncthreads();
            }

            #pragma unroll
            for (int mt = 0; mt < 4; mt++) {
                #pragma unroll
                for (int nt = 0; nt < 4; nt++) {
                    int col = n0 + wn * 32 + nt * 8 + c_in;
                    float bb0 = bias_[col], bb1 = bias_[col + 1];
                    size_t row0 = m0 + wm * 64 + mt * 16 + r_in;
                    float v00 = acc[mt][nt][0] + bb0, v01 = acc[mt][nt][1] + bb1;
                    float v10 = acc[mt][nt][2] + bb0, v11 = acc[mt][nt][3] + bb1;
                    if (relu) {
                        v00 = fmaxf(v00, 0.f); v01 = fmaxf(v01, 0.f);
                        v10 = fmaxf(v10, 0.f); v11 = fmaxf(v11, 0.f);
                    }
                    if (outF) {
                        float2 p0, p1;
                        p0.x = v00; p0.y = v01; p1.x = v10; p1.y = v11;
                        *(float2*)&outF[row0 * outN + col] = p0;
                        *(float2*)&outF[(row0 + 8) * outN + col] = p1;
                    } else {
                        uint32_t lo0, lo1;
                        uint32_t hi0 = pack_hi2(v00, v01, lo0);
                        uint32_t hi1 = pack_hi2(v10, v11, lo1);
                        *(uint32_t*)&outHi[row0 * outN + col] = hi0;
                        *(uint32_t*)&outLo[row0 * outN + col] = lo0;
                        *(uint32_t*)&outHi[(row0 + 8) * outN + col] = hi1;
                        *(uint32_t*)&outLo[(row0 + 8) * outN + col] = lo1;
                    }
                }
            }
        };

        // ---- producer stream: per t, 8 fc1a + 4 fc1b + 12 gi tiles ----
        const int nProd = TT * 24;
        for (int idx = wrk; idx < nProd; idx += NWORK) {
            int t = idx / 24;
            int r = idx - t * 24;
            if (r < 8) {
                // fc1a: x[t-rows] @ W1a^T -> a1 (bf16 split), relu
                int mh = r >> 2, nq = r & 3;
                size_t m0 = (size_t)t * 256 + (size_t)mh * 128;
                do_tile(xhi, xlo, m0, 256, 4, w1a_hi, w1a_lo, nq * 128, b1a,
                        nullptr, a1_hi, a1_lo, 512, true);
                bump_cnt(facnt + t * 32);
            } else if (r < 12) {
                // fc1b: a1 @ W1b^T (K=512) -> a2 (bf16 split), relu
                int rr = r - 8;
                int mh = rr >> 1, nq = rr & 1;
                spin_cnt(facnt + t * 32, 8u);
                size_t m0 = (size_t)t * 256 + (size_t)mh * 128;
                do_tile(a1_hi, a1_lo, m0, 512, 8, w1b_hi, w1b_lo, nq * 128, b1b,
                        nullptr, a2_hi, a2_lo, 256, true);
                bump_cnt(fbcnt + t * 32);
            } else {
                // gi: a2 @ Wih^T -> GI (fp32)
                int rr = r - 12;
                int mh = rr >= 6 ? 1 : 0;
                int nq = rr - mh * 6;
                spin_cnt(fbcnt + t * 32, 4u);
                size_t m0 = (size_t)t * 256 + (size_t)mh * 128;
                do_tile(a2_hi, a2_lo, m0, 256, 4, wih_hi, wih_lo, nq * 128, bih,
                        GI_, nullptr, nullptr, 768, false);
                bump_cnt(gicnt + t * 32);
            }
        }

        // ---- fc2a phase (gated on GRU h-flags) ----
        const int nTiles = TT * 8;
        for (int tile = wrk; tile < nTiles; tile += NWORK) {
            const int t = tile >> 3;
            const int mhalf = (tile >> 2) & 1;
            const int nq = tile & 3;

            {
                const unsigned int target = (unsigned int)(t + 1);
                if (tid < 64) {
                    unsigned int* f = flags + (((mhalf * 32) + (tid >> 1)) * 2 + (tid & 1)) * 32;
                    unsigned int v;
                    do {
                        asm volatile("ld.acquire.gpu.u32 %0, [%1];"
                            : "=r"(v) : "l"(f) : "memory");
                    } while (v < target);
                }
                __syncthreads();
            }

            size_t m0 = (size_t)t * 256 + (size_t)mhalf * 128;
            do_tile(HHI_, HLO_, m0, 256, 4, w2a_hi, w2a_lo, nq * 128, b2a,
                    buf1, nullptr, nullptr, 512, true);
        }
    }
}

// -------------------- fc2b head -------------------------------------------
__global__ void __launch_bounds__(256, 2) head_gemm(
    const float* __restrict__ A,
    const float* __restrict__ Wb,
    const float* __restrict__ bias,
    float* __restrict__ out, int M)
{
    __shared__ float Ws[18][512];
    const int tid = threadIdx.x;
    #pragma unroll
    for (int i = 0; i < 9; i++) {
        int idx = tid + 256 * i;
        ((float4*)&Ws[0][0])[idx] = ((const float4*)Wb)[idx];
    }
    __syncthreads();

    const size_t mbase = (size_t)blockIdx.x * 1024 + tid;

    float acc[4][18];
    #pragma unroll
    for (int i = 0; i < 4; i++)
        #pragma unroll
        for (int j = 0; j < 18; j++) acc[i][j] = 0.f;

    for (int k4 = 0; k4 < 128; k4++) {
        float4 a[4];
        #pragma unroll
        for (int i = 0; i < 4; i++)
            a[i] = *(const float4*)&A[(mbase + 256 * i) * 512 + k4 * 4];
        #pragma unroll
        for (int j = 0; j < 18; j++) {
            float4 w = *(const float4*)&Ws[j][k4 * 4];
            #pragma unroll
            for (int i = 0; i < 4; i++) {
                acc[i][j] += a[i].x * w.x;
                acc[i][j] += a[i].y * w.y;
                acc[i][j] += a[i].z * w.z;
                acc[i][j] += a[i].w * w.w;
            }
        }
    }

    #pragma unroll
    for (int i = 0; i < 4; i++) {
        size_t row = mbase + 256 * i;
        #pragma unroll
        for (int j = 0; j < 18; j++)
            out[row * 18 + j] = acc[i][j] + bias[j];
    }
}

// -------------------- launch ------------------------------------------------
extern "C" void kernel_launch(void* const* d_in, const int* in_sizes, int n_in,
                              void* d_out, int out_size)
{
    (void)in_sizes; (void)n_in; (void)out_size;
    const float* x    = (const float*)d_in[0];
    const float* W1a  = (const float*)d_in[1];
    const float* b1a  = (const float*)d_in[2];
    const float* W1b  = (const float*)d_in[3];
    const float* b1b  = (const float*)d_in[4];
    const float* Wih  = (const float*)d_in[5];
    const float* bih  = (const float*)d_in[6];
    const float* Whh  = (const float*)d_in[7];
    const float* bhh  = (const float*)d_in[8];
    const float* W2a  = (const float*)d_in[9];
    const float* b2a  = (const float*)d_in[10];
    const float* W2b  = (const float*)d_in[11];
    const float* b2b  = (const float*)d_in[12];
    float* out = (float*)d_out;

    float *buf1, *GI;
    __nv_bfloat16 *XHI, *XLO, *A1HI, *A1LO, *A2HI, *A2LO, *HHI, *HLO;
    __nv_bfloat16 *W1AHI, *W1ALO, *W1BHI, *W1BLO, *WIHHI, *WIHLO, *W2AHI, *W2ALO, *WHHHI, *WHHLO;
    unsigned int *FLAGS, *GICNT, *FACNT, *FBCNT;

    cudaGetSymbolAddress((void**)&buf1, d_buf1);
    cudaGetSymbolAddress((void**)&GI,   d_GI);
    cudaGetSymbolAddress((void**)&XHI,  d_XHI);  cudaGetSymbolAddress((void**)&XLO,  d_XLO);
    cudaGetSymbolAddress((void**)&A1HI, d_A1HI); cudaGetSymbolAddress((void**)&A1LO, d_A1LO);
    cudaGetSymbolAddress((void**)&A2HI, d_A2HI); cudaGetSymbolAddress((void**)&A2LO, d_A2LO);
    cudaGetSymbolAddress((void**)&HHI,  d_HHI);  cudaGetSymbolAddress((void**)&HLO,  d_HLO);
    cudaGetSymbolAddress((void**)&W1AHI, d_W1AHI); cudaGetSymbolAddress((void**)&W1ALO, d_W1ALO);
    cudaGetSymbolAddress((void**)&W1BHI, d_W1BHI); cudaGetSymbolAddress((void**)&W1BLO, d_W1BLO);
    cudaGetSymbolAddress((void**)&WIHHI, d_WIHHI); cudaGetSymbolAddress((void**)&WIHLO, d_WIHLO);
    cudaGetSymbolAddress((void**)&W2AHI, d_W2AHI); cudaGetSymbolAddress((void**)&W2ALO, d_W2ALO);
    cudaGetSymbolAddress((void**)&WHHHI, d_WHHHI); cudaGetSymbolAddress((void**)&WHHLO, d_WHHLO);
    cudaGetSymbolAddress((void**)&FLAGS, d_flags);
    cudaGetSymbolAddress((void**)&GICNT, d_gicnt);
    cudaGetSymbolAddress((void**)&FACNT, d_facnt);
    cudaGetSymbolAddress((void**)&FBCNT, d_fbcnt);

    cudaFuncSetAttribute(gru_persist, cudaFuncAttributeMaxDynamicSharedMemorySize, U_SM_TOTAL);

    const int M = MTOT;

    // ---- pre-split inputs/weights to bf16 hi/lo ----
    split_f32<<<(M * 256 / 4 + 255) / 256, 256>>>((const float4*)x, (uint2*)XHI, (uint2*)XLO, M * 256 / 4);
    split_f32<<<128, 256>>>((const float4*)W1a, (uint2*)W1AHI, (uint2*)W1ALO, 512 * 256 / 4);
    split_f32<<<128, 256>>>((const float4*)W1b, (uint2*)W1BHI, (uint2*)W1BLO, 256 * 512 / 4);
    split_f32<<<192, 256>>>((const float4*)Wih, (uint2*)WIHHI, (uint2*)WIHLO, 768 * 256 / 4);
    split_f32<<<128, 256>>>((const float4*)W2a, (uint2*)W2AHI, (uint2*)W2ALO, 512 * 256 / 4);
    split_f32<<<192, 256>>>((const float4*)Whh, (uint2*)WHHHI, (uint2*)WHHLO, 768 * 256 / 4);

    zero_u32<<<16, 256>>>((uint32_t*)FLAGS, NCTA_GRU * 2 * 32);
    zero_u32<<<64, 256>>>((uint32_t*)GICNT, TT * 32);
    zero_u32<<<64, 256>>>((uint32_t*)FACNT, TT * 32);
    zero_u32<<<64, 256>>>((uint32_t*)FBCNT, TT * 32);

    // ---- single persistent kernel: fc1a/fc1b/gi/GRU/fc2a (148 CTAs) ----
    gru_persist<<<NCTA_ALL, 256, U_SM_TOTAL>>>(
        GI, WHHHI, WHHLO, bhh, HHI, HLO, FLAGS, W2AHI, W2ALO, b2a, buf1,
        A2HI, A2LO, WIHHI, WIHLO, bih, GICNT,
        XHI, XLO, W1AHI, W1ALO, b1a, A1HI, A1LO,
        W1BHI, W1BLO, b1b, FACNT, FBCNT);

    // head
    head_gemm<<<M / 1024, 256>>>(buf1, W2b, b2b, out, M);
}

// round 15
// speedup vs baseline: 2.0966x; 2.0966x over previous
#include <cuda_runtime.h>
#include <cuda_bf16.h>
#include <math.h>
#include <stdint.h>

// Problem constants
#define TT 512
#define BB 256
#define IN_DIM 256
#define H1 512
#define HH 256
#define OUT_DIM 18
#define MTOT (TT*BB)   // 131072
#define NCTA_GRU 64
#define NCTA_ALL 148
#define NWORK (NCTA_ALL - NCTA_GRU)   // 84
#define GRP 8          // CTAs per sync group
#define LAG_B 8        // fc1b t-lag in v-groups
#define LAG_G 16       // gi t-lag in v-groups

// -------------------- scratch (static device globals; no allocs) -----------
__device__ float d_buf1[(size_t)MTOT * 512];     // fc2a out (fp32, for head)
__device__ float d_GI  [(size_t)MTOT * 768];     // gi fp32

__device__ __nv_bfloat16 d_XHI[(size_t)MTOT * 256], d_XLO[(size_t)MTOT * 256];
__device__ __nv_bfloat16 d_A1HI[(size_t)MTOT * 512], d_A1LO[(size_t)MTOT * 512];
__device__ __nv_bfloat16 d_A2HI[(size_t)MTOT * 256], d_A2LO[(size_t)MTOT * 256];
__device__ __nv_bfloat16 d_HHI[(size_t)MTOT * 256], d_HLO[(size_t)MTOT * 256];

__device__ __nv_bfloat16 d_W1AHI[512*256], d_W1ALO[512*256];
__device__ __nv_bfloat16 d_W1BHI[256*512], d_W1BLO[256*512];
__device__ __nv_bfloat16 d_WIHHI[768*256], d_WIHLO[768*256];
__device__ __nv_bfloat16 d_W2AHI[512*256], d_W2ALO[512*256];
__device__ __nv_bfloat16 d_WHHHI[768*256], d_WHHLO[768*256];

// padded sync state: one 128B line per slot
__device__ unsigned int d_flags[NCTA_GRU * 2 * 32];
__device__ unsigned int d_gicnt[TT * 32];
__device__ unsigned int d_facnt[TT * 32];
__device__ unsigned int d_fbcnt[TT * 32];

// ==================== helpers ==============================================
__device__ __forceinline__ uint32_t smem_u32(const void* p) {
    uint32_t a;
    asm("{ .reg .u64 t; cvta.to.shared.u64 t, %1; cvt.u32.u64 %0, t; }"
        : "=r"(a) : "l"(p));
    return a;
}

__device__ __forceinline__ void ldsm4(uint32_t* r, uint32_t addr) {
    asm volatile("ldmatrix.sync.aligned.m8n8.x4.shared.b16 {%0,%1,%2,%3}, [%4];"
        : "=r"(r[0]), "=r"(r[1]), "=r"(r[2]), "=r"(r[3]) : "r"(addr));
}
__device__ __forceinline__ void ldsm2(uint32_t* r, uint32_t addr) {
    asm volatile("ldmatrix.sync.aligned.m8n8.x2.shared.b16 {%0,%1}, [%2];"
        : "=r"(r[0]), "=r"(r[1]) : "r"(addr));
}

__device__ __forceinline__ void mma16816(float* c, const uint32_t* a, const uint32_t* b) {
    asm volatile(
        "mma.sync.aligned.m16n8k16.row.col.f32.bf16.bf16.f32 "
        "{%0,%1,%2,%3}, {%4,%5,%6,%7}, {%8,%9}, {%0,%1,%2,%3};"
        : "+f"(c[0]), "+f"(c[1]), "+f"(c[2]), "+f"(c[3])
        : "r"(a[0]), "r"(a[1]), "r"(a[2]), "r"(a[3]), "r"(b[0]), "r"(b[1]));
}

__device__ __forceinline__ void cp16(uint32_t dst, const void* src) {
    asm volatile("cp.async.cg.shared.global [%0], [%1], 16;"
        :: "r"(dst), "l"(src) : "memory");
}
#define CP_COMMIT() asm volatile("cp.async.commit_group;" ::: "memory")
#define CP_WAIT0()  asm volatile("cp.async.wait_group 0;" ::: "memory")
#define CP_WAIT1()  asm volatile("cp.async.wait_group 1;" ::: "memory")
#define BARX(id)    asm volatile("bar.sync %0, 128;" :: "r"(id) : "memory")

__device__ __forceinline__ void split_bf16x4(float4 v, uint2& hv, uint2& lv) {
    __nv_bfloat16 h0 = __float2bfloat16(v.x);
    __nv_bfloat16 h1 = __float2bfloat16(v.y);
    __nv_bfloat16 h2 = __float2bfloat16(v.z);
    __nv_bfloat16 h3 = __float2bfloat16(v.w);
    __nv_bfloat16 l0 = __float2bfloat16(v.x - __bfloat162float(h0));
    __nv_bfloat16 l1 = __float2bfloat16(v.y - __bfloat162float(h1));
    __nv_bfloat16 l2 = __float2bfloat16(v.z - __bfloat162float(h2));
    __nv_bfloat16 l3 = __float2bfloat16(v.w - __bfloat162float(h3));
    hv.x = (uint32_t)__bfloat16_as_ushort(h0) | ((uint32_t)__bfloat16_as_ushort(h1) << 16);
    hv.y = (uint32_t)__bfloat16_as_ushort(h2) | ((uint32_t)__bfloat16_as_ushort(h3) << 16);
    lv.x = (uint32_t)__bfloat16_as_ushort(l0) | ((uint32_t)__bfloat16_as_ushort(l1) << 16);
    lv.y = (uint32_t)__bfloat16_as_ushort(l2) | ((uint32_t)__bfloat16_as_ushort(l3) << 16);
}

__device__ __forceinline__ uint32_t pack_hi2(float a, float b, uint32_t& lo) {
    __nv_bfloat16 ha = __float2bfloat16(a);
    __nv_bfloat16 hb = __float2bfloat16(b);
    __nv_bfloat16 la = __float2bfloat16(a - __bfloat162float(ha));
    __nv_bfloat16 lb = __float2bfloat16(b - __bfloat162float(hb));
    lo = (uint32_t)__bfloat16_as_ushort(la) | ((uint32_t)__bfloat16_as_ushort(lb) << 16);
    return (uint32_t)__bfloat16_as_ushort(ha) | ((uint32_t)__bfloat16_as_ushort(hb) << 16);
}

// -------------------- split / zero kernels ---------------------------------
__global__ void split_f32(const float4* __restrict__ in,
                          uint2* __restrict__ hi, uint2* __restrict__ lo, int n4) {
    int i = blockIdx.x * blockDim.x + threadIdx.x;
    if (i < n4) {
        uint2 h, l;
        split_bf16x4(in[i], h, l);
        hi[i] = h; lo[i] = l;
    }
}
__global__ void zero_u32(uint32_t* p, int n) {
    int i = blockIdx.x * blockDim.x + threadIdx.x;
    if (i < n) p[i] = 0u;
}

// ==================== persistent everything kernel ==========================
// 148 CTAs: 0-63 GRU producers (R12 code); 64-147 workers running a LAGGED
// t-pipelined producer stream (fc1a[v] | fc1b[v-8] | gi[v-16]) then fc2a.
#define GROW 144
#define G_AHI 0
#define G_ALO 18432
#define G_BHI 36864
#define G_BLO 55296
#define G_STAGE 73728
#define G_SM_TOTAL (2*G_STAGE)

#define U_WHI 0
#define U_WLO 50688            // 96*528
#define U_HA_HI 101376         // 16*528 = 8448 each
#define U_HA_LO 109824
#define U_HB_HI 118272
#define U_HB_LO 126720
#define U_GHA 135168           // 16*97*4 = 6208
#define U_GHB 141376
#define U_SM_TOTAL 147584      // >= G_SM_TOTAL for worker path
#define USTRIDE 528

__global__ void __launch_bounds__(256, 1) gru_persist(
    float* __restrict__ GI_,
    const __nv_bfloat16* __restrict__ whh_hi,
    const __nv_bfloat16* __restrict__ whh_lo,
    const float* __restrict__ bhh,
    __nv_bfloat16* __restrict__ HHI_,
    __nv_bfloat16* __restrict__ HLO_,
    unsigned int* __restrict__ flags,
    const __nv_bfloat16* __restrict__ w2a_hi,
    const __nv_bfloat16* __restrict__ w2a_lo,
    const float* __restrict__ b2a,
    float* __restrict__ buf1,
    __nv_bfloat16* __restrict__ a2_hi,
    __nv_bfloat16* __restrict__ a2_lo,
    const __nv_bfloat16* __restrict__ wih_hi,
    const __nv_bfloat16* __restrict__ wih_lo,
    const float* __restrict__ bih,
    unsigned int* __restrict__ gicnt,
    const __nv_bfloat16* __restrict__ xhi,
    const __nv_bfloat16* __restrict__ xlo,
    const __nv_bfloat16* __restrict__ w1a_hi,
    const __nv_bfloat16* __restrict__ w1a_lo,
    const float* __restrict__ b1a,
    __nv_bfloat16* __restrict__ a1_hi,
    __nv_bfloat16* __restrict__ a1_lo,
    const __nv_bfloat16* __restrict__ w1b_hi,
    const __nv_bfloat16* __restrict__ w1b_lo,
    const float* __restrict__ b1b,
    unsigned int* __restrict__ facnt,
    unsigned int* __restrict__ fbcnt)
{
    extern __shared__ char sm[];
    const uint32_t smb = smem_u32(sm);
    const int tid = threadIdx.x;
    const int lane = tid & 31;
    const int wid = tid >> 5;
    const int cta = blockIdx.x;

    if (cta < NCTA_GRU) {
        // ==================== GRU producer path (R12, proven) ===============
        const int grpB = wid >> 2;
        const int gtid = tid & 127;
        const int wn = wid & 3;
        const int grp = cta >> 3;
        const int kq  = cta & 7;
        const int b0 = grp * 32;
        const int k0 = kq * 32;
        const int barid = 1 + grpB;

        float* GHg = (float*)(sm + (grpB ? U_GHB : U_GHA));
        const uint32_t hHiBuf = smb + (grpB ? U_HB_HI : U_HA_HI);
        const uint32_t hLoBuf = smb + (grpB ? U_HB_LO : U_HA_LO);
        const int bOff = grpB ? 16 : 0;

        for (int i = tid; i < 3072; i += 256) {
            int j = i >> 5;
            int c = i & 31;
            int gate = j >> 5, jr = j & 31;
            size_t soff = (size_t)(gate * 256 + k0 + jr) * 256 + c * 8;
            uint32_t d = (uint32_t)(j * USTRIDE + c * 16);
            cp16(smb + U_WHI + d, whh_hi + soff);
            cp16(smb + U_WLO + d, whh_lo + soff);
        }
        CP_COMMIT();

        {
            float* GA = (float*)(sm + U_GHA);
            float* GB = (float*)(sm + U_GHB);
            for (int i = tid; i < 16 * 97; i += 256) { GA[i] = 0.f; GB[i] = 0.f; }
        }

        int bloc[4], kloc[4];
        size_t off_o[4], gio[4];
        float brr[4], brz[4], brn[4], hp[4];
        #pragma unroll
        for (int i = 0; i < 4; i++) {
            int idx = gtid + 128 * i;
            int b = idx >> 5, ko = idx & 31;
            bloc[i] = b; kloc[i] = ko;
            int kg = k0 + ko;
            off_o[i] = (size_t)(b0 + bOff + b) * 256 + kg;
            gio[i] = (size_t)(b0 + bOff + b) * 768 + kg;
            brr[i] = bhh[kg];
            brz[i] = bhh[256 + kg];
            brn[i] = bhh[512 + kg];
            hp[i] = 0.f;
        }

        const uint32_t a_row = (uint32_t)(lane & 15);
        const uint32_t a_kb  = (uint32_t)((lane >> 4) * 16);
        const uint32_t b_row = (uint32_t)(((lane >> 4) & 1) * 8 + (lane & 7));
        const uint32_t b_kb  = (uint32_t)(((lane >> 3) & 1) * 16);
        const uint32_t b2_row = (uint32_t)(lane & 7);
        const uint32_t b2_kb  = (uint32_t)(((lane >> 3) & 1) * 16);

        const uint32_t aHi = hHiBuf + a_row * USTRIDE + a_kb;
        const uint32_t aLo = hLoBuf + a_row * USTRIDE + a_kb;
        const uint32_t bBaseHi4 = smb + U_WHI + (uint32_t)(wn * 24 + b_row) * USTRIDE + b_kb;
        const uint32_t bBaseLo4 = smb + U_WLO + (uint32_t)(wn * 24 + b_row) * USTRIDE + b_kb;
        const uint32_t bBaseHi2 = smb + U_WHI + (uint32_t)(wn * 24 + 16 + b2_row) * USTRIDE + b2_kb;
        const uint32_t bBaseLo2 = smb + U_WLO + (uint32_t)(wn * 24 + 16 + b2_row) * USTRIDE + b2_kb;

        unsigned int* myflag = flags + (cta * 2 + grpB) * 32;
        unsigned int* poll   = flags + (((grp * GRP) + (gtid & 7)) * 2 + grpB) * 32;

        auto do_mma = [&]() {
            float acc[3][4];
            #pragma unroll
            for (int i = 0; i < 3; i++)
                #pragma unroll
                for (int e = 0; e < 4; e++) acc[i][e] = 0.f;

            #pragma unroll 4
            for (int ks = 0; ks < 16; ks++) {
                const uint32_t koff = (uint32_t)(ks * 32);
                uint32_t a[4], bh[3][2], bl[3][2], r4[4];

                ldsm4(a, aHi + koff);
                ldsm4(r4, bBaseHi4 + koff);
                bh[0][0] = r4[0]; bh[0][1] = r4[1]; bh[1][0] = r4[2]; bh[1][1] = r4[3];
                ldsm2(bh[2], bBaseHi2 + koff);
                #pragma unroll
                for (int nt = 0; nt < 3; nt++) mma16816(acc[nt], a, bh[nt]);

                ldsm4(r4, bBaseLo4 + koff);
                bl[0][0] = r4[0]; bl[0][1] = r4[1]; bl[1][0] = r4[2]; bl[1][1] = r4[3];
                ldsm2(bl[2], bBaseLo2 + koff);
                #pragma unroll
                for (int nt = 0; nt < 3; nt++) mma16816(acc[nt], a, bl[nt]);

                ldsm4(a, aLo + koff);
                #pragma unroll
                for (int nt = 0; nt < 3; nt++) mma16816(acc[nt], a, bh[nt]);
            }
            const int r0 = lane >> 2;
            const int cc = (lane & 3) * 2;
            #pragma unroll
            for (int nt = 0; nt < 3; nt++) {
                int col = wn * 24 + nt * 8 + cc;
                GHg[r0 * 97 + col]           = acc[nt][0];
                GHg[r0 * 97 + col + 1]       = acc[nt][1];
                GHg[(r0 + 8) * 97 + col]     = acc[nt][2];
                GHg[(r0 + 8) * 97 + col + 1] = acc[nt][3];
            }
        };

        float ir[4], iz[4], in_[4];
        auto wait_gi = [&](int t) {
            const unsigned int* c = gicnt + t * 32;
            unsigned int v;
            do {
                asm volatile("ld.acquire.gpu.u32 %0, [%1];"
                    : "=r"(v) : "l"(c) : "memory");
            } while (v < 12u);
        };
        auto prefetch_gi = [&](int t) {
            const float* gin = GI_ + (size_t)t * (BB * 768);
            #pragma unroll
            for (int i = 0; i < 4; i++) {
                ir[i]  = __ldg(gin + gio[i]);
                iz[i]  = __ldg(gin + gio[i] + 256);
                in_[i] = __ldg(gin + gio[i] + 512);
            }
        };

        auto do_gates = [&](int t) {
            __nv_bfloat16* hoh = HHI_ + (size_t)t * (BB * HH);
            __nv_bfloat16* hol = HLO_ + (size_t)t * (BB * HH);
            #pragma unroll
            for (int i = 0; i < 4; i++) {
                int b = bloc[i], ko = kloc[i];
                float hr = GHg[b * 97 + ko]      + brr[i];
                float hz = GHg[b * 97 + 32 + ko] + brz[i];
                float hn = GHg[b * 97 + 64 + ko] + brn[i];

                float r = 1.f / (1.f + __expf(-(ir[i] + hr)));
                float z = 1.f / (1.f + __expf(-(iz[i] + hz)));
                float n = tanhf(in_[i] + r * hn);
                float hnew = (1.f - z) * n + z * hp[i];
                hp[i] = hnew;

                __nv_bfloat16 hh = __float2bfloat16(hnew);
                hoh[off_o[i]] = hh;
                hol[off_o[i]] = __float2bfloat16(hnew - __bfloat162float(hh));
            }
        };

        auto load_h = [&](int t) {
            const __nv_bfloat16* hph = HHI_ + (size_t)t * (BB * HH);
            const __nv_bfloat16* hpl = HLO_ + (size_t)t * (BB * HH);
            #pragma unroll
            for (int i = 0; i < 4; i++) {
                int idx = gtid + 128 * i;
                int r = idx >> 5;
                int c = idx & 31;
                size_t soff = (size_t)(b0 + bOff + r) * 256 + c * 8;
                uint32_t d = (uint32_t)(r * USTRIDE + c * 16);
                cp16(hHiBuf + d, hph + soff);
                cp16(hLoBuf + d, hpl + soff);
            }
            CP_COMMIT();
        };

        auto signal_spin = [&](unsigned int target) {
            BARX(barid);
            if (gtid == 0) {
                asm volatile("st.release.gpu.u32 [%0], %1;"
                    :: "l"(myflag), "r"(target) : "memory");
            }
            if (gtid < GRP) {
                unsigned int v;
                do {
                    asm volatile("ld.acquire.gpu.u32 %0, [%1];"
                        : "=r"(v) : "l"(poll) : "memory");
                } while (v < target);
            }
            BARX(barid);
        };

        CP_WAIT0();
        __syncthreads();

        wait_gi(0);
        prefetch_gi(0);
        do_gates(0);
        wait_gi(1);
        prefetch_gi(1);
        signal_spin(1u);
        load_h(0);

        for (int t = 1; t < TT; t++) {
            CP_WAIT0();
            BARX(barid);
            do_mma();
            BARX(barid);
            do_gates(t);
            if (t + 1 < TT) {
                wait_gi(t + 1);
                prefetch_gi(t + 1);
                signal_spin((unsigned int)(t + 1));
                load_h(t);
            }
        }
        BARX(barid);
        if (gtid == 0) {
            asm volatile("st.release.gpu.u32 [%0], %1;"
                :: "l"(myflag), "r"((unsigned int)TT) : "memory");
        }
    } else {
        // ==================== worker path ===================================
        const int wrk = cta - NCTA_GRU;
        const int wm = wid & 1;
        const int wn = wid >> 1;
        const uint32_t a_row = (uint32_t)(lane & 15);
        const uint32_t a_kb  = (uint32_t)((lane >> 4) * 16);
        const uint32_t b_row = (uint32_t)(((lane >> 4) & 1) * 8 + (lane & 7));
        const uint32_t b_kb  = (uint32_t)(((lane >> 3) & 1) * 16);
        const int r_in = lane >> 2;
        const int c_in = (lane & 3) * 2;

        auto spin_cnt = [&](unsigned int* c, unsigned int tgt) {
            if (tid == 0) {
                unsigned int v;
                do {
                    asm volatile("ld.acquire.gpu.u32 %0, [%1];"
                        : "=r"(v) : "l"(c) : "memory");
                } while (v < tgt);
            }
            __syncthreads();
        };
        auto bump_cnt = [&](unsigned int* c) {
            __threadfence();
            __syncthreads();
            if (tid == 0)
                asm volatile("red.release.gpu.global.add.u32 [%0], %1;"
                    :: "l"(c), "r"(1u) : "memory");
        };

        // generic 128x128xK bf16-split tile
        auto do_tile = [&](const __nv_bfloat16* Ahi_, const __nv_bfloat16* Alo_,
                           size_t m0, int Ks, int nch,
                           const __nv_bfloat16* Bhi_, const __nv_bfloat16* Blo_,
                           int n0, const float* bias_,
                           float* outF, __nv_bfloat16* outHi, __nv_bfloat16* outLo,
                           int outN, bool relu) {
            float acc[4][4][4];
            #pragma unroll
            for (int i = 0; i < 4; i++)
                #pragma unroll
                for (int j = 0; j < 4; j++)
                    #pragma unroll
                    for (int e = 0; e < 4; e++) acc[i][j][e] = 0.f;

            auto load_chunk = [&](int kc, int st) {
                const int kb = kc << 6;
                const uint32_t base = smb + (uint32_t)st * G_STAGE;
                #pragma unroll
                for (int j = 0; j < 4; j++) {
                    int idx = tid + 256 * j;
                    int r = idx >> 3;
                    int c = idx & 7;
                    size_t aoff = (m0 + r) * (size_t)Ks + kb + c * 8;
                    size_t boff = (size_t)(n0 + r) * Ks + kb + c * 8;
                    uint32_t d = (uint32_t)(r * GROW + c * 16);
                    cp16(base + G_AHI + d, Ahi_ + aoff);
                    cp16(base + G_ALO + d, Alo_ + aoff);
                    cp16(base + G_BHI + d, Bhi_ + boff);
                    cp16(base + G_BLO + d, Blo_ + boff);
                }
                CP_COMMIT();
            };

            load_chunk(0, 0);
            for (int kc = 0; kc < nch; kc++) {
                const int st = kc & 1;
                if (kc + 1 < nch) { load_chunk(kc + 1, st ^ 1); CP_WAIT1(); }
                else              { CP_WAIT0(); }
                __syncthreads();

                const uint32_t base = smb + (uint32_t)st * G_STAGE;
                #pragma unroll
                for (int ks = 0; ks < 4; ks++) {
                    const uint32_t koff = (uint32_t)(ks * 32);
                    uint32_t afr[4][4], bhi2[4][2], blo2[4][2];

                    #pragma unroll
                    for (int mt = 0; mt < 4; mt++)
                        ldsm4(afr[mt], base + G_AHI + (uint32_t)(wm*64 + mt*16 + a_row)*GROW + koff + a_kb);
                    #pragma unroll
                    for (int g = 0; g < 2; g++) {
                        uint32_t r4[4];
                        ldsm4(r4, base + G_BHI + (uint32_t)(wn*32 + g*16 + b_row)*GROW + koff + b_kb);
                        bhi2[g*2  ][0] = r4[0]; bhi2[g*2  ][1] = r4[1];
                        bhi2[g*2+1][0] = r4[2]; bhi2[g*2+1][1] = r4[3];
                    }
                    #pragma unroll
                    for (int mt = 0; mt < 4; mt++)
                        #pragma unroll
                        for (int nt = 0; nt < 4; nt++)
                            mma16816(acc[mt][nt], afr[mt], bhi2[nt]);

                    #pragma unroll
                    for (int g = 0; g < 2; g++) {
                        uint32_t r4[4];
                        ldsm4(r4, base + G_BLO + (uint32_t)(wn*32 + g*16 + b_row)*GROW + koff + b_kb);
                        blo2[g*2  ][0] = r4[0]; blo2[g*2  ][1] = r4[1];
                        blo2[g*2+1][0] = r4[2]; blo2[g*2+1][1] = r4[3];
                    }
                    #pragma unroll
                    for (int mt = 0; mt < 4; mt++)
                        #pragma unroll
                        for (int nt = 0; nt < 4; nt++)
                            mma16816(acc[mt][nt], afr[mt], blo2[nt]);

                    #pragma unroll
                    for (int mt = 0; mt < 4; mt++)
                        ldsm4(afr[mt], base + G_ALO + (uint32_t)(wm*64 + mt*16 + a_row)*GROW + koff + a_kb);
                    #pragma unroll
                    for (int mt = 0; mt < 4; mt++)
                        #pragma unroll
                        for (int nt = 0; nt < 4; nt++)
                            mma16816(acc[mt][nt], afr[mt], bhi2[nt]);
                }
                __syncthreads();
            }

            #pragma unroll
            for (int mt = 0; mt < 4; mt++) {
                #pragma unroll
                for (int nt = 0; nt < 4; nt++) {
                    int col = n0 + wn * 32 + nt * 8 + c_in;
                    float bb0 = bias_[col], bb1 = bias_[col + 1];
                    size_t row0 = m0 + wm * 64 + mt * 16 + r_in;
                    float v00 = acc[mt][nt][0] + bb0, v01 = acc[mt][nt][1] + bb1;
                    float v10 = acc[mt][nt][2] + bb0, v11 = acc[mt][nt][3] + bb1;
                    if (relu) {
                        v00 = fmaxf(v00, 0.f); v01 = fmaxf(v01, 0.f);
                        v10 = fmaxf(v10, 0.f); v11 = fmaxf(v11, 0.f);
                    }
                    if (outF) {
                        float2 p0, p1;
                        p0.x = v00; p0.y = v01; p1.x = v10; p1.y = v11;
                        *(float2*)&outF[row0 * outN + col] = p0;
                        *(float2*)&outF[(row0 + 8) * outN + col] = p1;
                    } else {
                        uint32_t lo0, lo1;
                        uint32_t hi0 = pack_hi2(v00, v01, lo0);
                        uint32_t hi1 = pack_hi2(v10, v11, lo1);
                        *(uint32_t*)&outHi[row0 * outN + col] = hi0;
                        *(uint32_t*)&outLo[row0 * outN + col] = lo0;
                        *(uint32_t*)&outHi[(row0 + 8) * outN + col] = hi1;
                        *(uint32_t*)&outLo[(row0 + 8) * outN + col] = lo1;
                    }
                }
            }
        };

        // ---- lagged producer stream: at v emit fc1a[v], fc1b[v-8], gi[v-16]
        const int nV = TT + LAG_G;            // 528 v-groups
        const int nProd = nV * 24;
        for (int idx = wrk; idx < nProd; idx += NWORK) {
            int v = idx / 24;
            int r = idx - v * 24;
            if (r < 8) {
                int t = v;
                if (t < TT) {
                    int mh = r >> 2, nq = r & 3;
                    size_t m0 = (size_t)t * 256 + (size_t)mh * 128;
                    do_tile(xhi, xlo, m0, 256, 4, w1a_hi, w1a_lo, nq * 128, b1a,
                            nullptr, a1_hi, a1_lo, 512, true);
                    bump_cnt(facnt + t * 32);
                }
            } else if (r < 12) {
                int t = v - LAG_B;
                if (t >= 0 && t < TT) {
                    int rr = r - 8;
                    int mh = rr >> 1, nq = rr & 1;
                    spin_cnt(facnt + t * 32, 8u);
                    size_t m0 = (size_t)t * 256 + (size_t)mh * 128;
                    do_tile(a1_hi, a1_lo, m0, 512, 8, w1b_hi, w1b_lo, nq * 128, b1b,
                            nullptr, a2_hi, a2_lo, 256, true);
                    bump_cnt(fbcnt + t * 32);
                }
            } else {
                int t = v - LAG_G;
                if (t >= 0 && t < TT) {
                    int rr = r - 12;
                    int mh = rr >= 6 ? 1 : 0;
                    int nq = rr - mh * 6;
                    spin_cnt(fbcnt + t * 32, 4u);
                    size_t m0 = (size_t)t * 256 + (size_t)mh * 128;
                    do_tile(a2_hi, a2_lo, m0, 256, 4, wih_hi, wih_lo, nq * 128, bih,
                            GI_, nullptr, nullptr, 768, false);
                    bump_cnt(gicnt + t * 32);
                }
            }
        }

        // ---- fc2a phase (gated on GRU h-flags) ----
        const int nTiles = TT * 8;
        for (int tile = wrk; tile < nTiles; tile += NWORK) {
            const int t = tile >> 3;
            const int mhalf = (tile >> 2) & 1;
            const int nq = tile & 3;

            {
                const unsigned int target = (unsigned int)(t + 1);
                if (tid < 64) {
                    unsigned int* f = flags + (((mhalf * 32) + (tid >> 1)) * 2 + (tid & 1)) * 32;
                    unsigned int v;
                    do {
                        asm volatile("ld.acquire.gpu.u32 %0, [%1];"
                            : "=r"(v) : "l"(f) : "memory");
                    } while (v < target);
                }
                __syncthreads();
            }

            size_t m0 = (size_t)t * 256 + (size_t)mhalf * 128;
            do_tile(HHI_, HLO_, m0, 256, 4, w2a_hi, w2a_lo, nq * 128, b2a,
                    buf1, nullptr, nullptr, 512, true);
        }
    }
}

// -------------------- fc2b head -------------------------------------------
__global__ void __launch_bounds__(256, 2) head_gemm(
    const float* __restrict__ A,
    const float* __restrict__ Wb,
    const float* __restrict__ bias,
    float* __restrict__ out, int M)
{
    __shared__ float Ws[18][512];
    const int tid = threadIdx.x;
    #pragma unroll
    for (int i = 0; i < 9; i++) {
        int idx = tid + 256 * i;
        ((float4*)&Ws[0][0])[idx] = ((const float4*)Wb)[idx];
    }
    __syncthreads();

    const size_t mbase = (size_t)blockIdx.x * 1024 + tid;

    float acc[4][18];
    #pragma unroll
    for (int i = 0; i < 4; i++)
        #pragma unroll
        for (int j = 0; j < 18; j++) acc[i][j] = 0.f;

    for (int k4 = 0; k4 < 128; k4++) {
        float4 a[4];
        #pragma unroll
        for (int i = 0; i < 4; i++)
            a[i] = *(const float4*)&A[(mbase + 256 * i) * 512 + k4 * 4];
        #pragma unroll
        for (int j = 0; j < 18; j++) {
            float4 w = *(const float4*)&Ws[j][k4 * 4];
            #pragma unroll
            for (int i = 0; i < 4; i++) {
                acc[i][j] += a[i].x * w.x;
                acc[i][j] += a[i].y * w.y;
                acc[i][j] += a[i].z * w.z;
                acc[i][j] += a[i].w * w.w;
            }
        }
    }

    #pragma unroll
    for (int i = 0; i < 4; i++) {
        size_t row = mbase + 256 * i;
        #pragma unroll
        for (int j = 0; j < 18; j++)
            out[row * 18 + j] = acc[i][j] + bias[j];
    }
}

// -------------------- launch ------------------------------------------------
extern "C" void kernel_launch(void* const* d_in, const int* in_sizes, int n_in,
                              void* d_out, int out_size)
{
    (void)in_sizes; (void)n_in; (void)out_size;
    const float* x    = (const float*)d_in[0];
    const float* W1a  = (const float*)d_in[1];
    const float* b1a  = (const float*)d_in[2];
    const float* W1b  = (const float*)d_in[3];
    const float* b1b  = (const float*)d_in[4];
    const float* Wih  = (const float*)d_in[5];
    const float* bih  = (const float*)d_in[6];
    const float* Whh  = (const float*)d_in[7];
    const float* bhh  = (const float*)d_in[8];
    const float* W2a  = (const float*)d_in[9];
    const float* b2a  = (const float*)d_in[10];
    const float* W2b  = (const float*)d_in[11];
    const float* b2b  = (const float*)d_in[12];
    float* out = (float*)d_out;

    float *buf1, *GI;
    __nv_bfloat16 *XHI, *XLO, *A1HI, *A1LO, *A2HI, *A2LO, *HHI, *HLO;
    __nv_bfloat16 *W1AHI, *W1ALO, *W1BHI, *W1BLO, *WIHHI, *WIHLO, *W2AHI, *W2ALO, *WHHHI, *WHHLO;
    unsigned int *FLAGS, *GICNT, *FACNT, *FBCNT;

    cudaGetSymbolAddress((void**)&buf1, d_buf1);
    cudaGetSymbolAddress((void**)&GI,   d_GI);
    cudaGetSymbolAddress((void**)&XHI,  d_XHI);  cudaGetSymbolAddress((void**)&XLO,  d_XLO);
    cudaGetSymbolAddress((void**)&A1HI, d_A1HI); cudaGetSymbolAddress((void**)&A1LO, d_A1LO);
    cudaGetSymbolAddress((void**)&A2HI, d_A2HI); cudaGetSymbolAddress((void**)&A2LO, d_A2LO);
    cudaGetSymbolAddress((void**)&HHI,  d_HHI);  cudaGetSymbolAddress((void**)&HLO,  d_HLO);
    cudaGetSymbolAddress((void**)&W1AHI, d_W1AHI); cudaGetSymbolAddress((void**)&W1ALO, d_W1ALO);
    cudaGetSymbolAddress((void**)&W1BHI, d_W1BHI); cudaGetSymbolAddress((void**)&W1BLO, d_W1BLO);
    cudaGetSymbolAddress((void**)&WIHHI, d_WIHHI); cudaGetSymbolAddress((void**)&WIHLO, d_WIHLO);
    cudaGetSymbolAddress((void**)&W2AHI, d_W2AHI); cudaGetSymbolAddress((void**)&W2ALO, d_W2ALO);
    cudaGetSymbolAddress((void**)&WHHHI, d_WHHHI); cudaGetSymbolAddress((void**)&WHHLO, d_WHHLO);
    cudaGetSymbolAddress((void**)&FLAGS, d_flags);
    cudaGetSymbolAddress((void**)&GICNT, d_gicnt);
    cudaGetSymbolAddress((void**)&FACNT, d_facnt);
    cudaGetSymbolAddress((void**)&FBCNT, d_fbcnt);

    cudaFuncSetAttribute(gru_persist, cudaFuncAttributeMaxDynamicSharedMemorySize, U_SM_TOTAL);

    const int M = MTOT;

    // ---- pre-split inputs/weights to bf16 hi/lo ----
    split_f32<<<(M * 256 / 4 + 255) / 256, 256>>>((const float4*)x, (uint2*)XHI, (uint2*)XLO, M * 256 / 4);
    split_f32<<<128, 256>>>((const float4*)W1a, (uint2*)W1AHI, (uint2*)W1ALO, 512 * 256 / 4);
    split_f32<<<128, 256>>>((const float4*)W1b, (uint2*)W1BHI, (uint2*)W1BLO, 256 * 512 / 4);
    split_f32<<<192, 256>>>((const float4*)Wih, (uint2*)WIHHI, (uint2*)WIHLO, 768 * 256 / 4);
    split_f32<<<128, 256>>>((const float4*)W2a, (uint2*)W2AHI, (uint2*)W2ALO, 512 * 256 / 4);
    split_f32<<<192, 256>>>((const float4*)Whh, (uint2*)WHHHI, (uint2*)WHHLO, 768 * 256 / 4);

    zero_u32<<<16, 256>>>((uint32_t*)FLAGS, NCTA_GRU * 2 * 32);
    zero_u32<<<64, 256>>>((uint32_t*)GICNT, TT * 32);
    zero_u32<<<64, 256>>>((uint32_t*)FACNT, TT * 32);
    zero_u32<<<64, 256>>>((uint32_t*)FBCNT, TT * 32);

    // ---- single persistent kernel: fc1a/fc1b/gi/GRU/fc2a (148 CTAs) ----
    gru_persist<<<NCTA_ALL, 256, U_SM_TOTAL>>>(
        GI, WHHHI, WHHLO, bhh, HHI, HLO, FLAGS, W2AHI, W2ALO, b2a, buf1,
        A2HI, A2LO, WIHHI, WIHLO, bih, GICNT,
        XHI, XLO, W1AHI, W1ALO, b1a, A1HI, A1LO,
        W1BHI, W1BLO, b1b, FACNT, FBCNT);

    // head
    head_gemm<<<M / 1024, 256>>>(buf1, W2b, b2b, out, M);
}

// round 16
// speedup vs baseline: 2.2505x; 1.0734x over previous
#include <cuda_runtime.h>
#include <cuda_bf16.h>
#include <math.h>
#include <stdint.h>

// Problem constants
#define TT 512
#define BB 256
#define IN_DIM 256
#define H1 512
#define HH 256
#define OUT_DIM 18
#define MTOT (TT*BB)   // 131072
#define NCTA_GRU 64
#define NCTA_ALL 148
#define NWORK (NCTA_ALL - NCTA_GRU)   // 84
#define GRP 8          // CTAs per sync group
#define LAG_B 8        // fc1b t-lag in v-groups
#define LAG_G 16       // gi t-lag in v-groups

// -------------------- scratch (static device globals; no allocs) -----------
__device__ float d_buf1[(size_t)MTOT * 512];     // fc2a out (fp32, for head)
__device__ float d_GI  [(size_t)MTOT * 768];     // gi fp32

__device__ __nv_bfloat16 d_XHI[(size_t)MTOT * 256], d_XLO[(size_t)MTOT * 256];
__device__ __nv_bfloat16 d_A1HI[(size_t)MTOT * 512], d_A1LO[(size_t)MTOT * 512];
__device__ __nv_bfloat16 d_A2HI[(size_t)MTOT * 256], d_A2LO[(size_t)MTOT * 256];
__device__ __nv_bfloat16 d_HHI[(size_t)MTOT * 256], d_HLO[(size_t)MTOT * 256];

__device__ __nv_bfloat16 d_W1AHI[512*256], d_W1ALO[512*256];
__device__ __nv_bfloat16 d_W1BHI[256*512], d_W1BLO[256*512];
__device__ __nv_bfloat16 d_WIHHI[768*256], d_WIHLO[768*256];
__device__ __nv_bfloat16 d_W2AHI[512*256], d_W2ALO[512*256];
__device__ __nv_bfloat16 d_WHHHI[768*256], d_WHHLO[768*256];

// padded sync state: one 128B line per slot
__device__ unsigned int d_flags[NCTA_GRU * 2 * 32];
__device__ unsigned int d_gicnt[TT * 32];
__device__ unsigned int d_facnt[TT * 32];
__device__ unsigned int d_fbcnt[TT * 32];
__device__ unsigned int d_fc2cnt[32];            // global fc2a ticket

// ==================== helpers ==============================================
__device__ __forceinline__ uint32_t smem_u32(const void* p) {
    uint32_t a;
    asm("{ .reg .u64 t; cvta.to.shared.u64 t, %1; cvt.u32.u64 %0, t; }"
        : "=r"(a) : "l"(p));
    return a;
}

__device__ __forceinline__ void ldsm4(uint32_t* r, uint32_t addr) {
    asm volatile("ldmatrix.sync.aligned.m8n8.x4.shared.b16 {%0,%1,%2,%3}, [%4];"
        : "=r"(r[0]), "=r"(r[1]), "=r"(r[2]), "=r"(r[3]) : "r"(addr));
}
__device__ __forceinline__ void ldsm2(uint32_t* r, uint32_t addr) {
    asm volatile("ldmatrix.sync.aligned.m8n8.x2.shared.b16 {%0,%1}, [%2];"
        : "=r"(r[0]), "=r"(r[1]) : "r"(addr));
}

__device__ __forceinline__ void mma16816(float* c, const uint32_t* a, const uint32_t* b) {
    asm volatile(
        "mma.sync.aligned.m16n8k16.row.col.f32.bf16.bf16.f32 "
        "{%0,%1,%2,%3}, {%4,%5,%6,%7}, {%8,%9}, {%0,%1,%2,%3};"
        : "+f"(c[0]), "+f"(c[1]), "+f"(c[2]), "+f"(c[3])
        : "r"(a[0]), "r"(a[1]), "r"(a[2]), "r"(a[3]), "r"(b[0]), "r"(b[1]));
}

__device__ __forceinline__ void cp16(uint32_t dst, const void* src) {
    asm volatile("cp.async.cg.shared.global [%0], [%1], 16;"
        :: "r"(dst), "l"(src) : "memory");
}
#define CP_COMMIT() asm volatile("cp.async.commit_group;" ::: "memory")
#define CP_WAIT0()  asm volatile("cp.async.wait_group 0;" ::: "memory")
#define CP_WAIT1()  asm volatile("cp.async.wait_group 1;" ::: "memory")
#define BARX(id)    asm volatile("bar.sync %0, 128;" :: "r"(id) : "memory")

__device__ __forceinline__ void split_bf16x4(float4 v, uint2& hv, uint2& lv) {
    __nv_bfloat16 h0 = __float2bfloat16(v.x);
    __nv_bfloat16 h1 = __float2bfloat16(v.y);
    __nv_bfloat16 h2 = __float2bfloat16(v.z);
    __nv_bfloat16 h3 = __float2bfloat16(v.w);
    __nv_bfloat16 l0 = __float2bfloat16(v.x - __bfloat162float(h0));
    __nv_bfloat16 l1 = __float2bfloat16(v.y - __bfloat162float(h1));
    __nv_bfloat16 l2 = __float2bfloat16(v.z - __bfloat162float(h2));
    __nv_bfloat16 l3 = __float2bfloat16(v.w - __bfloat162float(h3));
    hv.x = (uint32_t)__bfloat16_as_ushort(h0) | ((uint32_t)__bfloat16_as_ushort(h1) << 16);
    hv.y = (uint32_t)__bfloat16_as_ushort(h2) | ((uint32_t)__bfloat16_as_ushort(h3) << 16);
    lv.x = (uint32_t)__bfloat16_as_ushort(l0) | ((uint32_t)__bfloat16_as_ushort(l1) << 16);
    lv.y = (uint32_t)__bfloat16_as_ushort(l2) | ((uint32_t)__bfloat16_as_ushort(l3) << 16);
}

__device__ __forceinline__ uint32_t pack_hi2(float a, float b, uint32_t& lo) {
    __nv_bfloat16 ha = __float2bfloat16(a);
    __nv_bfloat16 hb = __float2bfloat16(b);
    __nv_bfloat16 la = __float2bfloat16(a - __bfloat162float(ha));
    __nv_bfloat16 lb = __float2bfloat16(b - __bfloat162float(hb));
    lo = (uint32_t)__bfloat16_as_ushort(la) | ((uint32_t)__bfloat16_as_ushort(lb) << 16);
    return (uint32_t)__bfloat16_as_ushort(ha) | ((uint32_t)__bfloat16_as_ushort(hb) << 16);
}

// -------------------- split / zero kernels ---------------------------------
__global__ void split_f32(const float4* __restrict__ in,
                          uint2* __restrict__ hi, uint2* __restrict__ lo, int n4) {
    int i = blockIdx.x * blockDim.x + threadIdx.x;
    if (i < n4) {
        uint2 h, l;
        split_bf16x4(in[i], h, l);
        hi[i] = h; lo[i] = l;
    }
}
__global__ void zero_u32(uint32_t* p, int n) {
    int i = blockIdx.x * blockDim.x + threadIdx.x;
    if (i < n) p[i] = 0u;
}

// ==================== shared tile GEMM (worker + pool) ======================
#define GROW 144
#define G_AHI 0
#define G_ALO 18432
#define G_BHI 36864
#define G_BLO 55296
#define G_STAGE 73728
#define G_SM_TOTAL (2*G_STAGE)
#define U_TICK 147512          // smem ticket slot (beyond staging)

__device__ __forceinline__ void tile_gemm(
    char* sm, uint32_t smb,
    const __nv_bfloat16* __restrict__ Ahi_, const __nv_bfloat16* __restrict__ Alo_,
    size_t m0, int Ks, int nch,
    const __nv_bfloat16* __restrict__ Bhi_, const __nv_bfloat16* __restrict__ Blo_,
    int n0, const float* __restrict__ bias_,
    float* __restrict__ outF, __nv_bfloat16* __restrict__ outHi,
    __nv_bfloat16* __restrict__ outLo, int outN, bool relu)
{
    const int tid = threadIdx.x;
    const int lane = tid & 31;
    const int wid = tid >> 5;
    const int wm = wid & 1;
    const int wn = wid >> 1;
    const uint32_t a_row = (uint32_t)(lane & 15);
    const uint32_t a_kb  = (uint32_t)((lane >> 4) * 16);
    const uint32_t b_row = (uint32_t)(((lane >> 4) & 1) * 8 + (lane & 7));
    const uint32_t b_kb  = (uint32_t)(((lane >> 3) & 1) * 16);
    const int r_in = lane >> 2;
    const int c_in = (lane & 3) * 2;

    float acc[4][4][4];
    #pragma unroll
    for (int i = 0; i < 4; i++)
        #pragma unroll
        for (int j = 0; j < 4; j++)
            #pragma unroll
            for (int e = 0; e < 4; e++) acc[i][j][e] = 0.f;

    auto load_chunk = [&](int kc, int st) {
        const int kb = kc << 6;
        const uint32_t base = smb + (uint32_t)st * G_STAGE;
        #pragma unroll
        for (int j = 0; j < 4; j++) {
            int idx = tid + 256 * j;
            int r = idx >> 3;
            int c = idx & 7;
            size_t aoff = (m0 + r) * (size_t)Ks + kb + c * 8;
            size_t boff = (size_t)(n0 + r) * Ks + kb + c * 8;
            uint32_t d = (uint32_t)(r * GROW + c * 16);
            cp16(base + G_AHI + d, Ahi_ + aoff);
            cp16(base + G_ALO + d, Alo_ + aoff);
            cp16(base + G_BHI + d, Bhi_ + boff);
            cp16(base + G_BLO + d, Blo_ + boff);
        }
        CP_COMMIT();
    };

    load_chunk(0, 0);
    for (int kc = 0; kc < nch; kc++) {
        const int st = kc & 1;
        if (kc + 1 < nch) { load_chunk(kc + 1, st ^ 1); CP_WAIT1(); }
        else              { CP_WAIT0(); }
        __syncthreads();

        const uint32_t base = smb + (uint32_t)st * G_STAGE;
        #pragma unroll
        for (int ks = 0; ks < 4; ks++) {
            const uint32_t koff = (uint32_t)(ks * 32);
            uint32_t afr[4][4], bhi2[4][2], blo2[4][2];

            #pragma unroll
            for (int mt = 0; mt < 4; mt++)
                ldsm4(afr[mt], base + G_AHI + (uint32_t)(wm*64 + mt*16 + a_row)*GROW + koff + a_kb);
            #pragma unroll
            for (int g = 0; g < 2; g++) {
                uint32_t r4[4];
                ldsm4(r4, base + G_BHI + (uint32_t)(wn*32 + g*16 + b_row)*GROW + koff + b_kb);
                bhi2[g*2  ][0] = r4[0]; bhi2[g*2  ][1] = r4[1];
                bhi2[g*2+1][0] = r4[2]; bhi2[g*2+1][1] = r4[3];
            }
            #pragma unroll
            for (int mt = 0; mt < 4; mt++)
                #pragma unroll
                for (int nt = 0; nt < 4; nt++)
                    mma16816(acc[mt][nt], afr[mt], bhi2[nt]);

            #pragma unroll
            for (int g = 0; g < 2; g++) {
                uint32_t r4[4];
                ldsm4(r4, base + G_BLO + (uint32_t)(wn*32 + g*16 + b_row)*GROW + koff + b_kb);
                blo2[g*2  ][0] = r4[0]; blo2[g*2  ][1] = r4[1];
                blo2[g*2+1][0] = r4[2]; blo2[g*2+1][1] = r4[3];
            }
            #pragma unroll
            for (int mt = 0; mt < 4; mt++)
                #pragma unroll
                for (int nt = 0; nt < 4; nt++)
                    mma16816(acc[mt][nt], afr[mt], blo2[nt]);

            #pragma unroll
            for (int mt = 0; mt < 4; mt++)
                ldsm4(afr[mt], base + G_ALO + (uint32_t)(wm*64 + mt*16 + a_row)*GROW + koff + a_kb);
            #pragma unroll
            for (int mt = 0; mt < 4; mt++)
                #pragma unroll
                for (int nt = 0; nt < 4; nt++)
                    mma16816(acc[mt][nt], afr[mt], bhi2[nt]);
        }
        __syncthreads();
    }

    #pragma unroll
    for (int mt = 0; mt < 4; mt++) {
        #pragma unroll
        for (int nt = 0; nt < 4; nt++) {
            int col = n0 + wn * 32 + nt * 8 + c_in;
            float bb0 = bias_[col], bb1 = bias_[col + 1];
            size_t row0 = m0 + wm * 64 + mt * 16 + r_in;
            float v00 = acc[mt][nt][0] + bb0, v01 = acc[mt][nt][1] + bb1;
            float v10 = acc[mt][nt][2] + bb0, v11 = acc[mt][nt][3] + bb1;
            if (relu) {
                v00 = fmaxf(v00, 0.f); v01 = fmaxf(v01, 0.f);
                v10 = fmaxf(v10, 0.f); v11 = fmaxf(v11, 0.f);
            }
            if (outF) {
                float2 p0, p1;
                p0.x = v00; p0.y = v01; p1.x = v10; p1.y = v11;
                *(float2*)&outF[row0 * outN + col] = p0;
                *(float2*)&outF[(row0 + 8) * outN + col] = p1;
            } else {
                uint32_t lo0, lo1;
                uint32_t hi0 = pack_hi2(v00, v01, lo0);
                uint32_t hi1 = pack_hi2(v10, v11, lo1);
                *(uint32_t*)&outHi[row0 * outN + col] = hi0;
                *(uint32_t*)&outLo[row0 * outN + col] = lo0;
                *(uint32_t*)&outHi[(row0 + 8) * outN + col] = hi1;
                *(uint32_t*)&outLo[(row0 + 8) * outN + col] = lo1;
            }
        }
    }
}

// ==================== persistent everything kernel ==========================
// 148 CTAs: 0-63 GRU producers (R12 code) which then JOIN the fc2a pool;
// 64-147 workers: lagged producer stream then the fc2a pool.
#define U_WHI 0
#define U_WLO 50688            // 96*528
#define U_HA_HI 101376         // 16*528 = 8448 each
#define U_HA_LO 109824
#define U_HB_HI 118272
#define U_HB_LO 126720
#define U_GHA 135168           // 16*97*4 = 6208
#define U_GHB 141376
#define U_SM_TOTAL 147584
#define USTRIDE 528

__global__ void __launch_bounds__(256, 1) gru_persist(
    float* __restrict__ GI_,
    const __nv_bfloat16* __restrict__ whh_hi,
    const __nv_bfloat16* __restrict__ whh_lo,
    const float* __restrict__ bhh,
    __nv_bfloat16* __restrict__ HHI_,
    __nv_bfloat16* __restrict__ HLO_,
    unsigned int* __restrict__ flags,
    const __nv_bfloat16* __restrict__ w2a_hi,
    const __nv_bfloat16* __restrict__ w2a_lo,
    const float* __restrict__ b2a,
    float* __restrict__ buf1,
    __nv_bfloat16* __restrict__ a2_hi,
    __nv_bfloat16* __restrict__ a2_lo,
    const __nv_bfloat16* __restrict__ wih_hi,
    const __nv_bfloat16* __restrict__ wih_lo,
    const float* __restrict__ bih,
    unsigned int* __restrict__ gicnt,
    const __nv_bfloat16* __restrict__ xhi,
    const __nv_bfloat16* __restrict__ xlo,
    const __nv_bfloat16* __restrict__ w1a_hi,
    const __nv_bfloat16* __restrict__ w1a_lo,
    const float* __restrict__ b1a,
    __nv_bfloat16* __restrict__ a1_hi,
    __nv_bfloat16* __restrict__ a1_lo,
    const __nv_bfloat16* __restrict__ w1b_hi,
    const __nv_bfloat16* __restrict__ w1b_lo,
    const float* __restrict__ b1b,
    unsigned int* __restrict__ facnt,
    unsigned int* __restrict__ fbcnt,
    unsigned int* __restrict__ fc2cnt)
{
    extern __shared__ char sm[];
    const uint32_t smb = smem_u32(sm);
    const int tid = threadIdx.x;
    const int lane = tid & 31;
    const int wid = tid >> 5;
    const int cta = blockIdx.x;

    if (cta < NCTA_GRU) {
        // ==================== GRU producer path (R12, proven) ===============
        const int grpB = wid >> 2;
        const int gtid = tid & 127;
        const int wn = wid & 3;
        const int grp = cta >> 3;
        const int kq  = cta & 7;
        const int b0 = grp * 32;
        const int k0 = kq * 32;
        const int barid = 1 + grpB;

        float* GHg = (float*)(sm + (grpB ? U_GHB : U_GHA));
        const uint32_t hHiBuf = smb + (grpB ? U_HB_HI : U_HA_HI);
        const uint32_t hLoBuf = smb + (grpB ? U_HB_LO : U_HA_LO);
        const int bOff = grpB ? 16 : 0;

        for (int i = tid; i < 3072; i += 256) {
            int j = i >> 5;
            int c = i & 31;
            int gate = j >> 5, jr = j & 31;
            size_t soff = (size_t)(gate * 256 + k0 + jr) * 256 + c * 8;
            uint32_t d = (uint32_t)(j * USTRIDE + c * 16);
            cp16(smb + U_WHI + d, whh_hi + soff);
            cp16(smb + U_WLO + d, whh_lo + soff);
        }
        CP_COMMIT();

        {
            float* GA = (float*)(sm + U_GHA);
            float* GB = (float*)(sm + U_GHB);
            for (int i = tid; i < 16 * 97; i += 256) { GA[i] = 0.f; GB[i] = 0.f; }
        }

        int bloc[4], kloc[4];
        size_t off_o[4], gio[4];
        float brr[4], brz[4], brn[4], hp[4];
        #pragma unroll
        for (int i = 0; i < 4; i++) {
            int idx = gtid + 128 * i;
            int b = idx >> 5, ko = idx & 31;
            bloc[i] = b; kloc[i] = ko;
            int kg = k0 + ko;
            off_o[i] = (size_t)(b0 + bOff + b) * 256 + kg;
            gio[i] = (size_t)(b0 + bOff + b) * 768 + kg;
            brr[i] = bhh[kg];
            brz[i] = bhh[256 + kg];
            brn[i] = bhh[512 + kg];
            hp[i] = 0.f;
        }

        const uint32_t a_row = (uint32_t)(lane & 15);
        const uint32_t a_kb  = (uint32_t)((lane >> 4) * 16);
        const uint32_t b_row = (uint32_t)(((lane >> 4) & 1) * 8 + (lane & 7));
        const uint32_t b_kb  = (uint32_t)(((lane >> 3) & 1) * 16);
        const uint32_t b2_row = (uint32_t)(lane & 7);
        const uint32_t b2_kb  = (uint32_t)(((lane >> 3) & 1) * 16);

        const uint32_t aHi = hHiBuf + a_row * USTRIDE + a_kb;
        const uint32_t aLo = hLoBuf + a_row * USTRIDE + a_kb;
        const uint32_t bBaseHi4 = smb + U_WHI + (uint32_t)(wn * 24 + b_row) * USTRIDE + b_kb;
        const uint32_t bBaseLo4 = smb + U_WLO + (uint32_t)(wn * 24 + b_row) * USTRIDE + b_kb;
        const uint32_t bBaseHi2 = smb + U_WHI + (uint32_t)(wn * 24 + 16 + b2_row) * USTRIDE + b2_kb;
        const uint32_t bBaseLo2 = smb + U_WLO + (uint32_t)(wn * 24 + 16 + b2_row) * USTRIDE + b2_kb;

        unsigned int* myflag = flags + (cta * 2 + grpB) * 32;
        unsigned int* poll   = flags + (((grp * GRP) + (gtid & 7)) * 2 + grpB) * 32;

        auto do_mma = [&]() {
            float acc[3][4];
            #pragma unroll
            for (int i = 0; i < 3; i++)
                #pragma unroll
                for (int e = 0; e < 4; e++) acc[i][e] = 0.f;

            #pragma unroll 4
            for (int ks = 0; ks < 16; ks++) {
                const uint32_t koff = (uint32_t)(ks * 32);
                uint32_t a[4], bh[3][2], bl[3][2], r4[4];

                ldsm4(a, aHi + koff);
                ldsm4(r4, bBaseHi4 + koff);
                bh[0][0] = r4[0]; bh[0][1] = r4[1]; bh[1][0] = r4[2]; bh[1][1] = r4[3];
                ldsm2(bh[2], bBaseHi2 + koff);
                #pragma unroll
                for (int nt = 0; nt < 3; nt++) mma16816(acc[nt], a, bh[nt]);

                ldsm4(r4, bBaseLo4 + koff);
                bl[0][0] = r4[0]; bl[0][1] = r4[1]; bl[1][0] = r4[2]; bl[1][1] = r4[3];
                ldsm2(bl[2], bBaseLo2 + koff);
                #pragma unroll
                for (int nt = 0; nt < 3; nt++) mma16816(acc[nt], a, bl[nt]);

                ldsm4(a, aLo + koff);
                #pragma unroll
                for (int nt = 0; nt < 3; nt++) mma16816(acc[nt], a, bh[nt]);
            }
            const int r0 = lane >> 2;
            const int cc = (lane & 3) * 2;
            #pragma unroll
            for (int nt = 0; nt < 3; nt++) {
                int col = wn * 24 + nt * 8 + cc;
                GHg[r0 * 97 + col]           = acc[nt][0];
                GHg[r0 * 97 + col + 1]       = acc[nt][1];
                GHg[(r0 + 8) * 97 + col]     = acc[nt][2];
                GHg[(r0 + 8) * 97 + col + 1] = acc[nt][3];
            }
        };

        float ir[4], iz[4], in_[4];
        auto wait_gi = [&](int t) {
            const unsigned int* c = gicnt + t * 32;
            unsigned int v;
            do {
                asm volatile("ld.acquire.gpu.u32 %0, [%1];"
                    : "=r"(v) : "l"(c) : "memory");
            } while (v < 12u);
        };
        auto prefetch_gi = [&](int t) {
            const float* gin = GI_ + (size_t)t * (BB * 768);
            #pragma unroll
            for (int i = 0; i < 4; i++) {
                ir[i]  = __ldg(gin + gio[i]);
                iz[i]  = __ldg(gin + gio[i] + 256);
                in_[i] = __ldg(gin + gio[i] + 512);
            }
        };

        auto do_gates = [&](int t) {
            __nv_bfloat16* hoh = HHI_ + (size_t)t * (BB * HH);
            __nv_bfloat16* hol = HLO_ + (size_t)t * (BB * HH);
            #pragma unroll
            for (int i = 0; i < 4; i++) {
                int b = bloc[i], ko = kloc[i];
                float hr = GHg[b * 97 + ko]      + brr[i];
                float hz = GHg[b * 97 + 32 + ko] + brz[i];
                float hn = GHg[b * 97 + 64 + ko] + brn[i];

                float r = 1.f / (1.f + __expf(-(ir[i] + hr)));
                float z = 1.f / (1.f + __expf(-(iz[i] + hz)));
                float n = tanhf(in_[i] + r * hn);
                float hnew = (1.f - z) * n + z * hp[i];
                hp[i] = hnew;

                __nv_bfloat16 hh = __float2bfloat16(hnew);
                hoh[off_o[i]] = hh;
                hol[off_o[i]] = __float2bfloat16(hnew - __bfloat162float(hh));
            }
        };

        auto load_h = [&](int t) {
            const __nv_bfloat16* hph = HHI_ + (size_t)t * (BB * HH);
            const __nv_bfloat16* hpl = HLO_ + (size_t)t * (BB * HH);
            #pragma unroll
            for (int i = 0; i < 4; i++) {
                int idx = gtid + 128 * i;
                int r = idx >> 5;
                int c = idx & 31;
                size_t soff = (size_t)(b0 + bOff + r) * 256 + c * 8;
                uint32_t d = (uint32_t)(r * USTRIDE + c * 16);
                cp16(hHiBuf + d, hph + soff);
                cp16(hLoBuf + d, hpl + soff);
            }
            CP_COMMIT();
        };

        auto signal_spin = [&](unsigned int target) {
            BARX(barid);
            if (gtid == 0) {
                asm volatile("st.release.gpu.u32 [%0], %1;"
                    :: "l"(myflag), "r"(target) : "memory");
            }
            if (gtid < GRP) {
                unsigned int v;
                do {
                    asm volatile("ld.acquire.gpu.u32 %0, [%1];"
                        : "=r"(v) : "l"(poll) : "memory");
                } while (v < target);
            }
            BARX(barid);
        };

        CP_WAIT0();
        __syncthreads();

        wait_gi(0);
        prefetch_gi(0);
        do_gates(0);
        wait_gi(1);
        prefetch_gi(1);
        signal_spin(1u);
        load_h(0);

        for (int t = 1; t < TT; t++) {
            CP_WAIT0();
            BARX(barid);
            do_mma();
            BARX(barid);
            do_gates(t);
            if (t + 1 < TT) {
                wait_gi(t + 1);
                prefetch_gi(t + 1);
                signal_spin((unsigned int)(t + 1));
                load_h(t);
            }
        }
        BARX(barid);
        if (gtid == 0) {
            asm volatile("st.release.gpu.u32 [%0], %1;"
                :: "l"(myflag), "r"((unsigned int)TT) : "memory");
        }
        // fall through to fc2a pool (smem reused as GEMM staging)
        __syncthreads();
    } else {
        // ==================== worker path ===================================
        const int wrk = cta - NCTA_GRU;

        auto spin_cnt = [&](unsigned int* c, unsigned int tgt) {
            if (tid == 0) {
                unsigned int v;
                do {
                    asm volatile("ld.acquire.gpu.u32 %0, [%1];"
                        : "=r"(v) : "l"(c) : "memory");
                } while (v < tgt);
            }
            __syncthreads();
        };
        auto bump_cnt = [&](unsigned int* c) {
            __threadfence();
            __syncthreads();
            if (tid == 0)
                asm volatile("red.release.gpu.global.add.u32 [%0], %1;"
                    :: "l"(c), "r"(1u) : "memory");
        };

        // ---- lagged producer stream: at v emit fc1a[v], fc1b[v-8], gi[v-16]
        const int nV = TT + LAG_G;
        const int nProd = nV * 24;
        for (int idx = wrk; idx < nProd; idx += NWORK) {
            int v = idx / 24;
            int r = idx - v * 24;
            if (r < 8) {
                int t = v;
                if (t < TT) {
                    int mh = r >> 2, nq = r & 3;
                    size_t m0 = (size_t)t * 256 + (size_t)mh * 128;
                    tile_gemm(sm, smb, xhi, xlo, m0, 256, 4,
                              w1a_hi, w1a_lo, nq * 128, b1a,
                              nullptr, a1_hi, a1_lo, 512, true);
                    bump_cnt(facnt + t * 32);
                }
            } else if (r < 12) {
                int t = v - LAG_B;
                if (t >= 0 && t < TT) {
                    int rr = r - 8;
                    int mh = rr >> 1, nq = rr & 1;
                    spin_cnt(facnt + t * 32, 8u);
                    size_t m0 = (size_t)t * 256 + (size_t)mh * 128;
                    tile_gemm(sm, smb, a1_hi, a1_lo, m0, 512, 8,
                              w1b_hi, w1b_lo, nq * 128, b1b,
                              nullptr, a2_hi, a2_lo, 256, true);
                    bump_cnt(fbcnt + t * 32);
                }
            } else {
                int t = v - LAG_G;
                if (t >= 0 && t < TT) {
                    int rr = r - 12;
                    int mh = rr >= 6 ? 1 : 0;
                    int nq = rr - mh * 6;
                    spin_cnt(fbcnt + t * 32, 4u);
                    size_t m0 = (size_t)t * 256 + (size_t)mh * 128;
                    tile_gemm(sm, smb, a2_hi, a2_lo, m0, 256, 4,
                              wih_hi, wih_lo, nq * 128, bih,
                              GI_, nullptr, nullptr, 768, false);
                    bump_cnt(gicnt + t * 32);
                }
            }
        }
        __syncthreads();
    }

    // ==================== fc2a pool: ALL 148 CTAs ===========================
    {
        unsigned int* tickp = (unsigned int*)(sm + U_TICK);
        const int nTiles = TT * 8;
        while (true) {
            __syncthreads();
            if (tid == 0) *tickp = atomicAdd(fc2cnt, 1u);
            __syncthreads();
            unsigned int tile = *tickp;
            if (tile >= (unsigned int)nTiles) break;

            const int t = tile >> 3;
            const int mhalf = (tile >> 2) & 1;
            const int nq = tile & 3;

            {
                const unsigned int target = (unsigned int)(t + 1);
                if (tid < 64) {
                    unsigned int* f = flags + (((mhalf * 32) + (tid >> 1)) * 2 + (tid & 1)) * 32;
                    unsigned int v;
                    do {
                        asm volatile("ld.acquire.gpu.u32 %0, [%1];"
                            : "=r"(v) : "l"(f) : "memory");
                    } while (v < target);
                }
                __syncthreads();
            }

            size_t m0 = (size_t)t * 256 + (size_t)mhalf * 128;
            tile_gemm(sm, smb, HHI_, HLO_, m0, 256, 4,
                      w2a_hi, w2a_lo, nq * 128, b2a,
                      buf1, nullptr, nullptr, 512, true);
        }
    }
}

// -------------------- fc2b head -------------------------------------------
__global__ void __launch_bounds__(256, 2) head_gemm(
    const float* __restrict__ A,
    const float* __restrict__ Wb,
    const float* __restrict__ bias,
    float* __restrict__ out, int M)
{
    __shared__ float Ws[18][512];
    const int tid = threadIdx.x;
    #pragma unroll
    for (int i = 0; i < 9; i++) {
        int idx = tid + 256 * i;
        ((float4*)&Ws[0][0])[idx] = ((const float4*)Wb)[idx];
    }
    __syncthreads();

    const size_t mbase = (size_t)blockIdx.x * 1024 + tid;

    float acc[4][18];
    #pragma unroll
    for (int i = 0; i < 4; i++)
        #pragma unroll
        for (int j = 0; j < 18; j++) acc[i][j] = 0.f;

    for (int k4 = 0; k4 < 128; k4++) {
        float4 a[4];
        #pragma unroll
        for (int i = 0; i < 4; i++)
            a[i] = *(const float4*)&A[(mbase + 256 * i) * 512 + k4 * 4];
        #pragma unroll
        for (int j = 0; j < 18; j++) {
            float4 w = *(const float4*)&Ws[j][k4 * 4];
            #pragma unroll
            for (int i = 0; i < 4; i++) {
                acc[i][j] += a[i].x * w.x;
                acc[i][j] += a[i].y * w.y;
                acc[i][j] += a[i].z * w.z;
                acc[i][j] += a[i].w * w.w;
            }
        }
    }

    #pragma unroll
    for (int i = 0; i < 4; i++) {
        size_t row = mbase + 256 * i;
        #pragma unroll
        for (int j = 0; j < 18; j++)
            out[row * 18 + j] = acc[i][j] + bias[j];
    }
}

// -------------------- launch ------------------------------------------------
extern "C" void kernel_launch(void* const* d_in, const int* in_sizes, int n_in,
                              void* d_out, int out_size)
{
    (void)in_sizes; (void)n_in; (void)out_size;
    const float* x    = (const float*)d_in[0];
    const float* W1a  = (const float*)d_in[1];
    const float* b1a  = (const float*)d_in[2];
    const float* W1b  = (const float*)d_in[3];
    const float* b1b  = (const float*)d_in[4];
    const float* Wih  = (const float*)d_in[5];
    const float* bih  = (const float*)d_in[6];
    const float* Whh  = (const float*)d_in[7];
    const float* bhh  = (const float*)d_in[8];
    const float* W2a  = (const float*)d_in[9];
    const float* b2a  = (const float*)d_in[10];
    const float* W2b  = (const float*)d_in[11];
    const float* b2b  = (const float*)d_in[12];
    float* out = (float*)d_out;

    float *buf1, *GI;
    __nv_bfloat16 *XHI, *XLO, *A1HI, *A1LO, *A2HI, *A2LO, *HHI, *HLO;
    __nv_bfloat16 *W1AHI, *W1ALO, *W1BHI, *W1BLO, *WIHHI, *WIHLO, *W2AHI, *W2ALO, *WHHHI, *WHHLO;
    unsigned int *FLAGS, *GICNT, *FACNT, *FBCNT, *FC2CNT;

    cudaGetSymbolAddress((void**)&buf1, d_buf1);
    cudaGetSymbolAddress((void**)&GI,   d_GI);
    cudaGetSymbolAddress((void**)&XHI,  d_XHI);  cudaGetSymbolAddress((void**)&XLO,  d_XLO);
    cudaGetSymbolAddress((void**)&A1HI, d_A1HI); cudaGetSymbolAddress((void**)&A1LO, d_A1LO);
    cudaGetSymbolAddress((void**)&A2HI, d_A2HI); cudaGetSymbolAddress((void**)&A2LO, d_A2LO);
    cudaGetSymbolAddress((void**)&HHI,  d_HHI);  cudaGetSymbolAddress((void**)&HLO,  d_HLO);
    cudaGetSymbolAddress((void**)&W1AHI, d_W1AHI); cudaGetSymbolAddress((void**)&W1ALO, d_W1ALO);
    cudaGetSymbolAddress((void**)&W1BHI, d_W1BHI); cudaGetSymbolAddress((void**)&W1BLO, d_W1BLO);
    cudaGetSymbolAddress((void**)&WIHHI, d_WIHHI); cudaGetSymbolAddress((void**)&WIHLO, d_WIHLO);
    cudaGetSymbolAddress((void**)&W2AHI, d_W2AHI); cudaGetSymbolAddress((void**)&W2ALO, d_W2ALO);
    cudaGetSymbolAddress((void**)&WHHHI, d_WHHHI); cudaGetSymbolAddress((void**)&WHHLO, d_WHHLO);
    cudaGetSymbolAddress((void**)&FLAGS, d_flags);
    cudaGetSymbolAddress((void**)&GICNT, d_gicnt);
    cudaGetSymbolAddress((void**)&FACNT, d_facnt);
    cudaGetSymbolAddress((void**)&FBCNT, d_fbcnt);
    cudaGetSymbolAddress((void**)&FC2CNT, d_fc2cnt);

    cudaFuncSetAttribute(gru_persist, cudaFuncAttributeMaxDynamicSharedMemorySize, U_SM_TOTAL);

    const int M = MTOT;

    // ---- pre-split inputs/weights to bf16 hi/lo ----
    split_f32<<<(M * 256 / 4 + 255) / 256, 256>>>((const float4*)x, (uint2*)XHI, (uint2*)XLO, M * 256 / 4);
    split_f32<<<128, 256>>>((const float4*)W1a, (uint2*)W1AHI, (uint2*)W1ALO, 512 * 256 / 4);
    split_f32<<<128, 256>>>((const float4*)W1b, (uint2*)W1BHI, (uint2*)W1BLO, 256 * 512 / 4);
    split_f32<<<192, 256>>>((const float4*)Wih, (uint2*)WIHHI, (uint2*)WIHLO, 768 * 256 / 4);
    split_f32<<<128, 256>>>((const float4*)W2a, (uint2*)W2AHI, (uint2*)W2ALO, 512 * 256 / 4);
    split_f32<<<192, 256>>>((const float4*)Whh, (uint2*)WHHHI, (uint2*)WHHLO, 768 * 256 / 4);

    zero_u32<<<16, 256>>>((uint32_t*)FLAGS, NCTA_GRU * 2 * 32);
    zero_u32<<<64, 256>>>((uint32_t*)GICNT, TT * 32);
    zero_u32<<<64, 256>>>((uint32_t*)FACNT, TT * 32);
    zero_u32<<<64, 256>>>((uint32_t*)FBCNT, TT * 32);
    zero_u32<<<1, 32>>>((uint32_t*)FC2CNT, 32);

    // ---- single persistent kernel: fc1a/fc1b/gi/GRU/fc2a (148 CTAs) ----
    gru_persist<<<NCTA_ALL, 256, U_SM_TOTAL>>>(
        GI, WHHHI, WHHLO, bhh, HHI, HLO, FLAGS, W2AHI, W2ALO, b2a, buf1,
        A2HI, A2LO, WIHHI, WIHLO, bih, GICNT,
        XHI, XLO, W1AHI, W1ALO, b1a, A1HI, A1LO,
        W1BHI, W1BLO, b1b, FACNT, FBCNT, FC2CNT);

    // head
    head_gemm<<<M / 1024, 256>>>(buf1, W2b, b2b, out, M);
}